// round 2
// baseline (speedup 1.0000x reference)
#include <cuda_runtime.h>

#define NN 40000
#define NE 640000
#define HID 128
#define NF 128
#define NG 50
#define TE 128
#define TN 128
#define THREADS 512

// device scratch (no allocations allowed)
__device__ float g_h[NN * NF];
__device__ float g_agg[NN * NF];

// bank-conflict-free transpose swizzle: row length fixed at 128 floats.
// phys = k*128 + ((e + 4k) & 127); float4 groups preserved (e multiple of 4).
__device__ __forceinline__ int swz(int k, int e) {
    return (k << 7) + ((e + (k << 2)) & 127);
}

// ShiftedSoftplus: softplus(x) - ln(2), numerically stable
__device__ __forceinline__ float sspf(float x) {
    return fmaxf(x, 0.0f) + log1pf(expf(-fabsf(x))) - 0.69314718055994530942f;
}

__global__ void zero_agg_kernel() {
    int i = blockIdx.x * blockDim.x + threadIdx.x;
    int stride = gridDim.x * blockDim.x;
    float4* p = (float4*)g_agg;
    const int n4 = NN * NF / 4;
    for (int idx = i; idx < n4; idx += stride)
        p[idx] = make_float4(0.f, 0.f, 0.f, 0.f);
}

// ---------------------------------------------------------------------------
// h = x @ lin1_w^T   (N x 128) @ (128 x 128), no bias
// Tile: 128 nodes x 128 filters per block, thread tile 4n x 8f.
// ---------------------------------------------------------------------------
__global__ __launch_bounds__(THREADS, 1)
void lin1_kernel(const float* __restrict__ x, const float* __restrict__ w, int N) {
    extern __shared__ float sm[];
    float* wt = sm;           // [k][f] transposed, 16384 floats
    float* xT = sm + 16384;   // [k][n] transposed, 16384 floats
    int tid = threadIdx.x;

    for (int idx = tid; idx < NF * HID; idx += THREADS) {
        int f = idx >> 7, k = idx & 127;          // w[f][k] coalesced read
        wt[swz(k, f)] = w[idx];
    }
    int nb = blockIdx.x * TN;
    for (int idx = tid; idx < TN * HID; idx += THREADS) {
        int n = idx >> 7, k = idx & 127;          // x[n][k] coalesced read
        float v = (nb + n < N) ? x[(nb + n) * HID + k] : 0.f;
        xT[swz(k, n)] = v;                        // conflict-free via swizzle
    }
    __syncthreads();

    int n0 = (tid >> 4) << 2;
    int f0 = (tid & 15) << 3;
    float acc[4][8];
#pragma unroll
    for (int i = 0; i < 4; i++)
#pragma unroll
        for (int j = 0; j < 8; j++) acc[i][j] = 0.f;

#pragma unroll 4
    for (int k = 0; k < HID; k++) {
        float4 av = *(const float4*)(xT + swz(k, n0));
        float4 wa = *(const float4*)(wt + swz(k, f0));
        float4 wb = *(const float4*)(wt + swz(k, f0 + 4));
        float ae[4] = {av.x, av.y, av.z, av.w};
        float wf[8] = {wa.x, wa.y, wa.z, wa.w, wb.x, wb.y, wb.z, wb.w};
#pragma unroll
        for (int i = 0; i < 4; i++)
#pragma unroll
            for (int j = 0; j < 8; j++)
                acc[i][j] = fmaf(ae[i], wf[j], acc[i][j]);
    }
#pragma unroll
    for (int i = 0; i < 4; i++) {
        int n = nb + n0 + i;
        if (n < N) {
            float4 v0 = {acc[i][0], acc[i][1], acc[i][2], acc[i][3]};
            float4 v1 = {acc[i][4], acc[i][5], acc[i][6], acc[i][7]};
            *(float4*)(g_h + n * NF + f0) = v0;
            *(float4*)(g_h + n * NF + f0 + 4) = v1;
        }
    }
}

// ---------------------------------------------------------------------------
// Fused edge kernel (persistent): per 128-edge tile
//   T = ssp(edge_attr @ w1^T + b1)        (GEMM1, K=50)
//   W = (T @ w2^T + b2) * envelope(C)     (GEMM2, K=128)
//   msg = h[src] * W ; atomicAdd(agg[dst], msg)
// ---------------------------------------------------------------------------
__global__ __launch_bounds__(THREADS, 1)
void edge_kernel(const float* __restrict__ ea,   // [E][50]
                 const int*   __restrict__ eidx, // [2][E]
                 const float* __restrict__ ew,   // [E]
                 const float* __restrict__ w1,   // [128][50]
                 const float* __restrict__ b1,   // [128]
                 const float* __restrict__ w2,   // [128][128]
                 const float* __restrict__ b2,   // [128]
                 int E)
{
    extern __shared__ float sm[];
    float* w1t  = sm;                  // [50][128]  : 6400
    float* w2t  = w1t + NG * NF;       // [128][128] : 16384
    float* AT   = w2t + NF * NF;       // [50][128]  : 6400
    float* Ts   = AT + NG * TE;        // [128][128] : 16384
    float* sC   = Ts + NF * TE;        // 128
    int*   ssrc = (int*)(sC + TE);     // 128
    int*   sdst = ssrc + TE;           // 128
    float* sb1  = (float*)(sdst + TE); // 128
    float* sb2  = sb1 + NF;            // 128

    int tid = threadIdx.x;

    // one-time per block: transposed weights + biases
    for (int idx = tid; idx < NF * NG; idx += THREADS) {
        int f = idx / NG, k = idx - f * NG;       // w1[f][k] coalesced
        w1t[swz(k, f)] = w1[idx];
    }
    for (int idx = tid; idx < NF * NF; idx += THREADS) {
        int f = idx >> 7, k = idx & 127;          // w2[f][k] coalesced
        w2t[swz(k, f)] = w2[idx];
    }
    if (tid < NF) { sb1[tid] = b1[tid]; sb2[tid] = b2[tid]; }
    __syncthreads();

    int e0 = (tid >> 4) << 2;   // 0..124
    int f0 = (tid & 15) << 3;   // 0..120

    int ntiles = (E + TE - 1) / TE;
    for (int tile = blockIdx.x; tile < ntiles; tile += gridDim.x) {
        int ebase = tile * TE;

        // tile loads (AT transposed + swizzled; conflict-free stores)
        for (int idx = tid; idx < TE * NG; idx += THREADS) {
            int e = idx / NG, k = idx - e * NG;   // ea coalesced
            float v = (ebase + e < E) ? ea[(ebase + e) * NG + k] : 0.f;
            AT[swz(k, e)] = v;
        }
        if (tid < TE) {
            int e = ebase + tid;
            if (e < E) {
                float wv = ew[e];
                sC[tid] = 0.5f * (cosf(wv * 0.31415926535897932f) + 1.0f);
                ssrc[tid] = eidx[e];
                sdst[tid] = eidx[E + e];
            } else {
                sC[tid] = 0.f; ssrc[tid] = 0; sdst[tid] = 0;
            }
        }
        __syncthreads();   // also guarantees prev tile's Ts reads are done

        // GEMM1: T[e][f] = sum_k A[e][k]*w1[f][k] + b1[f]
        float acc[4][8];
#pragma unroll
        for (int i = 0; i < 4; i++)
#pragma unroll
            for (int j = 0; j < 8; j++) acc[i][j] = sb1[f0 + j];

#pragma unroll 2
        for (int k = 0; k < NG; k++) {
            float4 av = *(const float4*)(AT + swz(k, e0));
            float4 wa = *(const float4*)(w1t + swz(k, f0));
            float4 wb = *(const float4*)(w1t + swz(k, f0 + 4));
            float ae[4] = {av.x, av.y, av.z, av.w};
            float wf[8] = {wa.x, wa.y, wa.z, wa.w, wb.x, wb.y, wb.z, wb.w};
#pragma unroll
            for (int i = 0; i < 4; i++)
#pragma unroll
                for (int j = 0; j < 8; j++)
                    acc[i][j] = fmaf(ae[i], wf[j], acc[i][j]);
        }

        // ssp + store T transposed (float4 stores along e)
#pragma unroll
        for (int j = 0; j < 8; j++) {
            float4 v = {sspf(acc[0][j]), sspf(acc[1][j]),
                        sspf(acc[2][j]), sspf(acc[3][j])};
            *(float4*)(Ts + swz(f0 + j, e0)) = v;
        }
        __syncthreads();

        // GEMM2: W[e][f] = sum_k T[e][k]*w2[f][k] + b2[f]
#pragma unroll
        for (int i = 0; i < 4; i++)
#pragma unroll
            for (int j = 0; j < 8; j++) acc[i][j] = sb2[f0 + j];

#pragma unroll 4
        for (int k = 0; k < NF; k++) {
            float4 tv = *(const float4*)(Ts + swz(k, e0));
            float4 wa = *(const float4*)(w2t + swz(k, f0));
            float4 wb = *(const float4*)(w2t + swz(k, f0 + 4));
            float te[4] = {tv.x, tv.y, tv.z, tv.w};
            float wf[8] = {wa.x, wa.y, wa.z, wa.w, wb.x, wb.y, wb.z, wb.w};
#pragma unroll
            for (int i = 0; i < 4; i++)
#pragma unroll
                for (int j = 0; j < 8; j++)
                    acc[i][j] = fmaf(te[i], wf[j], acc[i][j]);
        }

        // envelope * gather h[src] * scatter-add agg[dst]
#pragma unroll
        for (int i = 0; i < 4; i++) {
            int e = e0 + i;
            if (ebase + e < E) {
                float c = sC[e];
                int s = ssrc[e];
                int d = sdst[e];
                const float4* hp = (const float4*)(g_h + s * NF + f0);
                float4 ha = hp[0];
                float4 hb = hp[1];
                float* ap = g_agg + d * NF + f0;
                atomicAdd(ap + 0, acc[i][0] * c * ha.x);
                atomicAdd(ap + 1, acc[i][1] * c * ha.y);
                atomicAdd(ap + 2, acc[i][2] * c * ha.z);
                atomicAdd(ap + 3, acc[i][3] * c * ha.w);
                atomicAdd(ap + 4, acc[i][4] * c * hb.x);
                atomicAdd(ap + 5, acc[i][5] * c * hb.y);
                atomicAdd(ap + 6, acc[i][6] * c * hb.z);
                atomicAdd(ap + 7, acc[i][7] * c * hb.w);
            }
        }
        // next-iter loads are fenced by top __syncthreads()
    }
}

// ---------------------------------------------------------------------------
// out = ssp(agg @ lin2^T + lin2_b) @ lin_w^T + lin_b
// ---------------------------------------------------------------------------
__global__ __launch_bounds__(THREADS, 1)
void out_kernel(const float* __restrict__ w2,  // lin2_w [128][128]
                const float* __restrict__ b2,  // lin2_b
                const float* __restrict__ wo,  // lin_w  [128][128]
                const float* __restrict__ bo,  // lin_b
                float* __restrict__ out, int N)
{
    extern __shared__ float sm[];
    float* w2t = sm;             // 16384
    float* wot = sm + 16384;     // 16384
    float* buf = sm + 32768;     // 16384 (aggT then h2T)
    float* sb2 = sm + 49152;     // 128
    float* sbo = sm + 49280;     // 128
    int tid = threadIdx.x;

    for (int idx = tid; idx < NF * NF; idx += THREADS) {
        int f = idx >> 7, k = idx & 127;
        w2t[swz(k, f)] = w2[idx];
        wot[swz(k, f)] = wo[idx];
    }
    if (tid < NF) { sb2[tid] = b2[tid]; sbo[tid] = bo[tid]; }

    int nb = blockIdx.x * TN;
    for (int idx = tid; idx < TN * NF; idx += THREADS) {
        int n = idx >> 7, k = idx & 127;
        float v = (nb + n < N) ? g_agg[(nb + n) * NF + k] : 0.f;
        buf[swz(k, n)] = v;
    }
    __syncthreads();

    int n0 = (tid >> 4) << 2;
    int f0 = (tid & 15) << 3;
    float acc[4][8];
#pragma unroll
    for (int i = 0; i < 4; i++)
#pragma unroll
        for (int j = 0; j < 8; j++) acc[i][j] = sb2[f0 + j];

#pragma unroll 4
    for (int k = 0; k < NF; k++) {
        float4 av = *(const float4*)(buf + swz(k, n0));
        float4 wa = *(const float4*)(w2t + swz(k, f0));
        float4 wb = *(const float4*)(w2t + swz(k, f0 + 4));
        float ae[4] = {av.x, av.y, av.z, av.w};
        float wf[8] = {wa.x, wa.y, wa.z, wa.w, wb.x, wb.y, wb.z, wb.w};
#pragma unroll
        for (int i = 0; i < 4; i++)
#pragma unroll
            for (int j = 0; j < 8; j++)
                acc[i][j] = fmaf(ae[i], wf[j], acc[i][j]);
    }
    __syncthreads();   // all buf reads complete before overwrite

    // ssp + write h2 transposed back to buf
#pragma unroll
    for (int j = 0; j < 8; j++) {
        float4 v = {sspf(acc[0][j]), sspf(acc[1][j]),
                    sspf(acc[2][j]), sspf(acc[3][j])};
        *(float4*)(buf + swz(f0 + j, n0)) = v;
    }
    __syncthreads();

#pragma unroll
    for (int i = 0; i < 4; i++)
#pragma unroll
        for (int j = 0; j < 8; j++) acc[i][j] = sbo[f0 + j];

#pragma unroll 4
    for (int k = 0; k < HID; k++) {
        float4 av = *(const float4*)(buf + swz(k, n0));
        float4 wa = *(const float4*)(wot + swz(k, f0));
        float4 wb = *(const float4*)(wot + swz(k, f0 + 4));
        float ae[4] = {av.x, av.y, av.z, av.w};
        float wf[8] = {wa.x, wa.y, wa.z, wa.w, wb.x, wb.y, wb.z, wb.w};
#pragma unroll
        for (int i = 0; i < 4; i++)
#pragma unroll
            for (int j = 0; j < 8; j++)
                acc[i][j] = fmaf(ae[i], wf[j], acc[i][j]);
    }
#pragma unroll
    for (int i = 0; i < 4; i++) {
        int n = nb + n0 + i;
        if (n < N) {
            float4 v0 = {acc[i][0], acc[i][1], acc[i][2], acc[i][3]};
            float4 v1 = {acc[i][4], acc[i][5], acc[i][6], acc[i][7]};
            *(float4*)(out + n * HID + f0) = v0;
            *(float4*)(out + n * HID + f0 + 4) = v1;
        }
    }
}

// ---------------------------------------------------------------------------

extern "C" void kernel_launch(void* const* d_in, const int* in_sizes, int n_in,
                              void* d_out, int out_size) {
    const float* x      = (const float*)d_in[0];
    const int*   eidx   = (const int*)  d_in[1];
    const float* ew     = (const float*)d_in[2];
    const float* ea     = (const float*)d_in[3];
    const float* mlp_w1 = (const float*)d_in[4];
    const float* mlp_b1 = (const float*)d_in[5];
    const float* mlp_w2 = (const float*)d_in[6];
    const float* mlp_b2 = (const float*)d_in[7];
    const float* lin1_w = (const float*)d_in[8];
    const float* lin2_w = (const float*)d_in[9];
    const float* lin2_b = (const float*)d_in[10];
    const float* lin_w  = (const float*)d_in[11];
    const float* lin_b  = (const float*)d_in[12];
    float* out = (float*)d_out;

    int N = in_sizes[0] / HID;
    int E = in_sizes[2];

    const int EDGE_SMEM = (NG * NF + NF * NF + NG * TE + NF * TE + 5 * 128) * 4; // 184832
    const int LIN1_SMEM = 2 * NF * NF * 4;                                       // 131072
    const int OUT_SMEM  = (3 * NF * NF + 2 * 128) * 4;                           // 197632

    cudaFuncSetAttribute(edge_kernel, cudaFuncAttributeMaxDynamicSharedMemorySize, EDGE_SMEM);
    cudaFuncSetAttribute(lin1_kernel, cudaFuncAttributeMaxDynamicSharedMemorySize, LIN1_SMEM);
    cudaFuncSetAttribute(out_kernel,  cudaFuncAttributeMaxDynamicSharedMemorySize, OUT_SMEM);

    int ntile_n = (N + TN - 1) / TN;

    zero_agg_kernel<<<2048, 256>>>();
    lin1_kernel<<<ntile_n, THREADS, LIN1_SMEM>>>(x, lin1_w, N);
    edge_kernel<<<152, THREADS, EDGE_SMEM>>>(ea, eidx, ew,
                                             mlp_w1, mlp_b1, mlp_w2, mlp_b2, E);
    out_kernel<<<ntile_n, THREADS, OUT_SMEM>>>(lin2_w, lin2_b, lin_w, lin_b, out, N);
}

// round 4
// speedup vs baseline: 1.3976x; 1.3976x over previous
#include <cuda_runtime.h>

#define NN 40000
#define HID 128
#define NF 128
#define NG 50
#define TE 128
#define TN 128

typedef unsigned long long ull;

// device scratch (no allocations allowed)
__device__ float g_h[NN * NF];
__device__ float g_agg[NN * NF];

// XOR swizzle, conflict-safe for loads-along-row and transpose stores.
// Row length 128 floats; float4 groups preserved (XOR value is a multiple of 4).
__device__ __forceinline__ int xswz(int k, int e) {
    return (k << 7) + (e ^ ((k & 31) << 2));
}

// ---- packed f32x2 helpers (Blackwell FFMA2) --------------------------------
__device__ __forceinline__ ull pack2(float x) {
    ull r; unsigned xi = __float_as_uint(x);
    asm("mov.b64 %0, {%1, %1};" : "=l"(r) : "r"(xi));
    return r;
}
__device__ __forceinline__ void fma2(ull& d, ull a, ull b) {
    asm("fma.rn.f32x2 %0, %1, %2, %0;" : "+l"(d) : "l"(a), "l"(b));
}
__device__ __forceinline__ float2 unpk2(ull v) {
    unsigned lo, hi;
    asm("mov.b64 {%0, %1}, %2;" : "=r"(lo), "=r"(hi) : "l"(v));
    return make_float2(__uint_as_float(lo), __uint_as_float(hi));
}

// vector f32 reduction (sm_90+): 4 adds per instruction
__device__ __forceinline__ void red4(float* p, float a, float b, float c, float d) {
    asm volatile("red.global.add.v4.f32 [%0], {%1,%2,%3,%4};"
                 :: "l"(p), "f"(a), "f"(b), "f"(c), "f"(d) : "memory");
}

// MUFU fast exp2/log2 via PTX (compile to EX2/LG2 regardless of flags)
__device__ __forceinline__ float ex2f(float x) {
    float r; asm("ex2.approx.f32 %0, %1;" : "=f"(r) : "f"(x)); return r;
}
__device__ __forceinline__ float lg2f(float x) {
    float r; asm("lg2.approx.f32 %0, %1;" : "=f"(r) : "f"(x)); return r;
}
__device__ __forceinline__ float fcosf(float x) {
    float r; asm("cos.approx.f32 %0, %1;" : "=f"(r) : "f"(x)); return r;
}

// ShiftedSoftplus (stable): max(x,0) + ln2*(lg2(1 + 2^(-|x|*log2e)) - 1)
__device__ __forceinline__ float sspf(float x) {
    float t = ex2f(-fabsf(x) * 1.4426950408889634f);
    return fmaxf(x, 0.0f) + 0.69314718055994531f * (lg2f(1.0f + t) - 1.0f);
}

// ---- shared 8x8 packed GEMM inner loop -------------------------------------
// acc[i][j]: rows e0+i (i<8), col pairs (f0+2j, f0+2j+1) (j<4)
template<int K>
__device__ __forceinline__ void gemm8x8(const float* __restrict__ Asm,
                                        const float* __restrict__ Wsm,
                                        int e0, int f0, ull acc[8][4]) {
#pragma unroll 2
    for (int k = 0; k < K; k++) {
        float4 a0 = *(const float4*)(Asm + xswz(k, e0));
        float4 a1 = *(const float4*)(Asm + xswz(k, e0 + 4));
        ulonglong2 w0 = *(const ulonglong2*)(Wsm + xswz(k, f0));
        ulonglong2 w1 = *(const ulonglong2*)(Wsm + xswz(k, f0 + 4));
        ull wp0 = w0.x, wp1 = w0.y, wp2 = w1.x, wp3 = w1.y;
        float ae[8] = {a0.x, a0.y, a0.z, a0.w, a1.x, a1.y, a1.z, a1.w};
#pragma unroll
        for (int i = 0; i < 8; i++) {
            ull ap = pack2(ae[i]);
            fma2(acc[i][0], ap, wp0);
            fma2(acc[i][1], ap, wp1);
            fma2(acc[i][2], ap, wp2);
            fma2(acc[i][3], ap, wp3);
        }
    }
}

__global__ void zero_agg_kernel() {
    int i = blockIdx.x * blockDim.x + threadIdx.x;
    int stride = gridDim.x * blockDim.x;
    float4* p = (float4*)g_agg;
    const int n4 = NN * NF / 4;
    for (int idx = i; idx < n4; idx += stride)
        p[idx] = make_float4(0.f, 0.f, 0.f, 0.f);
}

// ---------------------------------------------------------------------------
// h = x @ lin1_w^T (no bias). 256 threads, tile 128x128, thread tile 8x8.
// ---------------------------------------------------------------------------
__global__ __launch_bounds__(256, 1)
void lin1_kernel(const float* __restrict__ x, const float* __restrict__ w, int N) {
    extern __shared__ float sm[];
    float* wt = sm;           // [k][f] 16384
    float* xT = sm + 16384;   // [k][n] 16384
    int tid = threadIdx.x;

    for (int idx = tid; idx < NF * HID; idx += 256) {
        int f = idx >> 7, k = idx & 127;
        wt[xswz(k, f)] = w[idx];
    }
    int nb = blockIdx.x * TN;
    for (int idx = tid; idx < TN * HID; idx += 256) {
        int n = idx >> 7, k = idx & 127;
        float v = (nb + n < N) ? x[(nb + n) * HID + k] : 0.f;
        xT[xswz(k, n)] = v;
    }
    __syncthreads();

    int n0 = (tid >> 4) << 3;
    int f0 = (tid & 15) << 3;
    ull acc[8][4];
#pragma unroll
    for (int i = 0; i < 8; i++)
#pragma unroll
        for (int j = 0; j < 4; j++) acc[i][j] = 0ull;

    gemm8x8<HID>(xT, wt, n0, f0, acc);

#pragma unroll
    for (int i = 0; i < 8; i++) {
        int n = nb + n0 + i;
        if (n < N) {
            float2 p0 = unpk2(acc[i][0]), p1 = unpk2(acc[i][1]);
            float2 p2 = unpk2(acc[i][2]), p3 = unpk2(acc[i][3]);
            *(float4*)(g_h + n * NF + f0)     = make_float4(p0.x, p0.y, p1.x, p1.y);
            *(float4*)(g_h + n * NF + f0 + 4) = make_float4(p2.x, p2.y, p3.x, p3.y);
        }
    }
}

// ---------------------------------------------------------------------------
// Fused edge kernel (persistent, 256 threads): per 128-edge tile
//   T = ssp(edge_attr @ w1^T + b1)        (GEMM1, K=50)
//   W = (T @ w2^T + b2) * envelope(C)     (GEMM2, K=128)
//   msg = h[src] * W ; red.v4(agg[dst], msg)
// ---------------------------------------------------------------------------
__global__ __launch_bounds__(256, 1)
void edge_kernel(const float* __restrict__ ea,   // [E][50]
                 const int*   __restrict__ eidx, // [2][E]
                 const float* __restrict__ ew,   // [E]
                 const float* __restrict__ w1,   // [128][50]
                 const float* __restrict__ b1,
                 const float* __restrict__ w2,   // [128][128]
                 const float* __restrict__ b2,
                 int E)
{
    extern __shared__ float sm[];
    float* w1t  = sm;                  // [50][128]  : 6400
    float* w2t  = w1t + NG * NF;       // [128][128] : 16384
    float* AT   = w2t + NF * NF;       // [50][128]  : 6400
    float* Ts   = AT + NG * TE;        // [128][128] : 16384
    float* sC   = Ts + NF * TE;        // 128
    int*   ssrc = (int*)(sC + TE);     // 128
    int*   sdst = ssrc + TE;           // 128
    float* sb1  = (float*)(sdst + TE); // 128
    float* sb2  = sb1 + NF;            // 128

    int tid = threadIdx.x;

    for (int idx = tid; idx < NF * NG; idx += 256) {
        int f = idx / NG, k = idx - f * NG;
        w1t[xswz(k, f)] = w1[idx];
    }
    for (int idx = tid; idx < NF * NF; idx += 256) {
        int f = idx >> 7, k = idx & 127;
        w2t[xswz(k, f)] = w2[idx];
    }
    if (tid < NF) { sb1[tid] = b1[tid]; sb2[tid] = b2[tid]; }
    __syncthreads();

    int e0 = (tid >> 4) << 3;   // 0..120
    int f0 = (tid & 15) << 3;   // 0..120
    const ull* b1p = (const ull*)(sb1 + f0);
    const ull* b2p = (const ull*)(sb2 + f0);

    int ntiles = (E + TE - 1) / TE;
    for (int tile = blockIdx.x; tile < ntiles; tile += gridDim.x) {
        int ebase = tile * TE;

        for (int idx = tid; idx < TE * NG; idx += 256) {
            int e = idx / NG, k = idx - e * NG;
            float v = (ebase + e < E) ? ea[(ebase + e) * NG + k] : 0.f;
            AT[xswz(k, e)] = v;
        }
        if (tid < TE) {
            int e = ebase + tid;
            if (e < E) {
                float wv = ew[e];
                sC[tid] = 0.5f * (fcosf(wv * 0.31415926535897932f) + 1.0f);
                ssrc[tid] = eidx[e];
                sdst[tid] = eidx[E + e];
            } else { sC[tid] = 0.f; ssrc[tid] = 0; sdst[tid] = 0; }
        }
        __syncthreads();   // AT ready; all prev-tile Ts reads complete

        // GEMM1
        ull acc[8][4];
#pragma unroll
        for (int i = 0; i < 8; i++)
#pragma unroll
            for (int j = 0; j < 4; j++) acc[i][j] = b1p[j];
        gemm8x8<NG>(AT, w1t, e0, f0, acc);

        // ssp + transpose-store into Ts
#pragma unroll
        for (int j = 0; j < 4; j++) {
            float2 v[8];
#pragma unroll
            for (int i = 0; i < 8; i++) v[i] = unpk2(acc[i][j]);
            int fA = f0 + 2 * j, fB = fA + 1;
            *(float4*)(Ts + xswz(fA, e0)) =
                make_float4(sspf(v[0].x), sspf(v[1].x), sspf(v[2].x), sspf(v[3].x));
            *(float4*)(Ts + xswz(fA, e0 + 4)) =
                make_float4(sspf(v[4].x), sspf(v[5].x), sspf(v[6].x), sspf(v[7].x));
            *(float4*)(Ts + xswz(fB, e0)) =
                make_float4(sspf(v[0].y), sspf(v[1].y), sspf(v[2].y), sspf(v[3].y));
            *(float4*)(Ts + xswz(fB, e0 + 4)) =
                make_float4(sspf(v[4].y), sspf(v[5].y), sspf(v[6].y), sspf(v[7].y));
        }
        __syncthreads();

        // GEMM2
#pragma unroll
        for (int i = 0; i < 8; i++)
#pragma unroll
            for (int j = 0; j < 4; j++) acc[i][j] = b2p[j];
        gemm8x8<NF>(Ts, w2t, e0, f0, acc);

        // envelope * gather h[src] * vector scatter-add agg[dst]
#pragma unroll
        for (int i = 0; i < 8; i++) {
            int e = e0 + i;
            if (ebase + e < E) {
                float c = sC[e];
                int s = ssrc[e], d = sdst[e];
                const float4* hp = (const float4*)(g_h + s * NF + f0);
                float4 ha = hp[0], hb = hp[1];
                float2 p0 = unpk2(acc[i][0]), p1 = unpk2(acc[i][1]);
                float2 p2 = unpk2(acc[i][2]), p3 = unpk2(acc[i][3]);
                float* ap = g_agg + d * NF + f0;
                red4(ap,     p0.x * c * ha.x, p0.y * c * ha.y,
                             p1.x * c * ha.z, p1.y * c * ha.w);
                red4(ap + 4, p2.x * c * hb.x, p2.y * c * hb.y,
                             p3.x * c * hb.z, p3.y * c * hb.w);
            }
        }
    }
}

// ---------------------------------------------------------------------------
// out = ssp(agg @ lin2^T + b2) @ lin_w^T + bo. 256 threads, 8x8.
// ---------------------------------------------------------------------------
__global__ __launch_bounds__(256, 1)
void out_kernel(const float* __restrict__ w2, const float* __restrict__ b2,
                const float* __restrict__ wo, const float* __restrict__ bo,
                float* __restrict__ out, int N)
{
    extern __shared__ float sm[];
    float* w2t = sm;             // 16384
    float* wot = sm + 16384;     // 16384
    float* buf = sm + 32768;     // 16384
    float* sb2 = sm + 49152;     // 128
    float* sbo = sm + 49280;     // 128
    int tid = threadIdx.x;

    for (int idx = tid; idx < NF * NF; idx += 256) {
        int f = idx >> 7, k = idx & 127;
        w2t[xswz(k, f)] = w2[idx];
        wot[xswz(k, f)] = wo[idx];
    }
    if (tid < NF) { sb2[tid] = b2[tid]; sbo[tid] = bo[tid]; }

    int nb = blockIdx.x * TN;
    for (int idx = tid; idx < TN * NF; idx += 256) {
        int n = idx >> 7, k = idx & 127;
        float v = (nb + n < N) ? g_agg[(nb + n) * NF + k] : 0.f;
        buf[xswz(k, n)] = v;
    }
    __syncthreads();

    int n0 = (tid >> 4) << 3;
    int f0 = (tid & 15) << 3;
    const ull* b2p = (const ull*)(sb2 + f0);
    const ull* bop = (const ull*)(sbo + f0);

    ull acc[8][4];
#pragma unroll
    for (int i = 0; i < 8; i++)
#pragma unroll
        for (int j = 0; j < 4; j++) acc[i][j] = b2p[j];
    gemm8x8<NF>(buf, w2t, n0, f0, acc);
    __syncthreads();   // all buf reads done before overwrite

    // ssp + transpose-store h2 into buf
#pragma unroll
    for (int j = 0; j < 4; j++) {
        float2 v[8];
#pragma unroll
        for (int i = 0; i < 8; i++) v[i] = unpk2(acc[i][j]);
        int fA = f0 + 2 * j, fB = fA + 1;
        *(float4*)(buf + xswz(fA, n0)) =
            make_float4(sspf(v[0].x), sspf(v[1].x), sspf(v[2].x), sspf(v[3].x));
        *(float4*)(buf + xswz(fA, n0 + 4)) =
            make_float4(sspf(v[4].x), sspf(v[5].x), sspf(v[6].x), sspf(v[7].x));
        *(float4*)(buf + xswz(fB, n0)) =
            make_float4(sspf(v[0].y), sspf(v[1].y), sspf(v[2].y), sspf(v[3].y));
        *(float4*)(buf + xswz(fB, n0 + 4)) =
            make_float4(sspf(v[4].y), sspf(v[5].y), sspf(v[6].y), sspf(v[7].y));
    }
    __syncthreads();

#pragma unroll
    for (int i = 0; i < 8; i++)
#pragma unroll
        for (int j = 0; j < 4; j++) acc[i][j] = bop[j];
    gemm8x8<HID>(buf, wot, n0, f0, acc);

#pragma unroll
    for (int i = 0; i < 8; i++) {
        int n = nb + n0 + i;
        if (n < N) {
            float2 p0 = unpk2(acc[i][0]), p1 = unpk2(acc[i][1]);
            float2 p2 = unpk2(acc[i][2]), p3 = unpk2(acc[i][3]);
            *(float4*)(out + n * HID + f0)     = make_float4(p0.x, p0.y, p1.x, p1.y);
            *(float4*)(out + n * HID + f0 + 4) = make_float4(p2.x, p2.y, p3.x, p3.y);
        }
    }
}

// ---------------------------------------------------------------------------

extern "C" void kernel_launch(void* const* d_in, const int* in_sizes, int n_in,
                              void* d_out, int out_size) {
    const float* x      = (const float*)d_in[0];
    const int*   eidx   = (const int*)  d_in[1];
    const float* ew     = (const float*)d_in[2];
    const float* ea     = (const float*)d_in[3];
    const float* mlp_w1 = (const float*)d_in[4];
    const float* mlp_b1 = (const float*)d_in[5];
    const float* mlp_w2 = (const float*)d_in[6];
    const float* mlp_b2 = (const float*)d_in[7];
    const float* lin1_w = (const float*)d_in[8];
    const float* lin2_w = (const float*)d_in[9];
    const float* lin2_b = (const float*)d_in[10];
    const float* lin_w  = (const float*)d_in[11];
    const float* lin_b  = (const float*)d_in[12];
    float* out = (float*)d_out;

    int N = in_sizes[0] / HID;
    int E = in_sizes[2];

    const int EDGE_SMEM = (NG * NF + NF * NF + NG * TE + NF * TE + 5 * 128) * 4;
    const int LIN1_SMEM = 2 * NF * NF * 4;
    const int OUT_SMEM  = (3 * NF * NF + 2 * 128) * 4;

    cudaFuncSetAttribute(edge_kernel, cudaFuncAttributeMaxDynamicSharedMemorySize, EDGE_SMEM);
    cudaFuncSetAttribute(lin1_kernel, cudaFuncAttributeMaxDynamicSharedMemorySize, LIN1_SMEM);
    cudaFuncSetAttribute(out_kernel,  cudaFuncAttributeMaxDynamicSharedMemorySize, OUT_SMEM);

    int ntile_n = (N + TN - 1) / TN;

    zero_agg_kernel<<<2048, 256>>>();
    lin1_kernel<<<ntile_n, 256, LIN1_SMEM>>>(x, lin1_w, N);
    edge_kernel<<<152, 256, EDGE_SMEM>>>(ea, eidx, ew,
                                         mlp_w1, mlp_b1, mlp_w2, mlp_b2, E);
    out_kernel<<<ntile_n, 256, OUT_SMEM>>>(lin2_w, lin2_b, lin_w, lin_b, out, N);
}

// round 5
// speedup vs baseline: 1.5643x; 1.1193x over previous
#include <cuda_runtime.h>

#define NN 40000
#define HID 128
#define NF 128
#define NG 50
#define TE 128
#define TN 128

typedef unsigned long long ull;

// device scratch (no allocations allowed)
__device__ float g_h[NN * NF];
__device__ float g_agg[NN * NF];

// XOR swizzle. Row length 128 floats. x(k)=4*((k^(k>>3))&31) is a multiple of 4
// (float4 groups preserved) and gives 8 distinct bank-groups within every
// 8-lane phase for transpose stores (k = 4*lane + j).
__device__ __forceinline__ int xswz(int k, int e) {
    return (k << 7) + (e ^ (((k ^ (k >> 3)) & 31) << 2));
}

// ---- packed f32x2 helpers (Blackwell FFMA2) --------------------------------
__device__ __forceinline__ ull pack2(float x) {
    ull r; unsigned xi = __float_as_uint(x);
    asm("mov.b64 %0, {%1, %1};" : "=l"(r) : "r"(xi));
    return r;
}
__device__ __forceinline__ void fma2(ull& d, ull a, ull b) {
    asm("fma.rn.f32x2 %0, %1, %2, %0;" : "+l"(d) : "l"(a), "l"(b));
}
__device__ __forceinline__ float2 unpk2(ull v) {
    unsigned lo, hi;
    asm("mov.b64 {%0, %1}, %2;" : "=r"(lo), "=r"(hi) : "l"(v));
    return make_float2(__uint_as_float(lo), __uint_as_float(hi));
}

// vector f32 reduction (sm_90+): 4 adds per instruction
__device__ __forceinline__ void red4(float* p, float a, float b, float c, float d) {
    asm volatile("red.global.add.v4.f32 [%0], {%1,%2,%3,%4};"
                 :: "l"(p), "f"(a), "f"(b), "f"(c), "f"(d) : "memory");
}

// MUFU fast exp2/log2/cos via PTX
__device__ __forceinline__ float ex2f(float x) {
    float r; asm("ex2.approx.f32 %0, %1;" : "=f"(r) : "f"(x)); return r;
}
__device__ __forceinline__ float lg2f(float x) {
    float r; asm("lg2.approx.f32 %0, %1;" : "=f"(r) : "f"(x)); return r;
}
__device__ __forceinline__ float fcosf(float x) {
    float r; asm("cos.approx.f32 %0, %1;" : "=f"(r) : "f"(x)); return r;
}

// ShiftedSoftplus (stable): max(x,0) + ln2*(lg2(1 + 2^(-|x|*log2e)) - 1)
__device__ __forceinline__ float sspf(float x) {
    float t = ex2f(-fabsf(x) * 1.4426950408889634f);
    return fmaxf(x, 0.0f) + 0.69314718055994531f * (lg2f(1.0f + t) - 1.0f);
}

// ---- packed GEMM inner loop, thread tile = 8 edges (4 pairs) x 4 filters ---
// acc[j][i]: filter f0+j, edge pair (e0+2i, e0+2i+1) packed (lo=even, hi=odd)
template<int K>
__device__ __forceinline__ void gemmP(const float* __restrict__ Asm,
                                      const float* __restrict__ Wsm,
                                      int e0, int f0, ull acc[4][4]) {
#pragma unroll 4
    for (int k = 0; k < K; k++) {
        // edge values natively packed in pairs (warp-uniform address: broadcast)
        ulonglong2 a01 = *(const ulonglong2*)(Asm + xswz(k, e0));
        ulonglong2 a23 = *(const ulonglong2*)(Asm + xswz(k, e0 + 4));
        float4 wv = *(const float4*)(Wsm + xswz(k, f0));
        ull ap[4] = {a01.x, a01.y, a23.x, a23.y};
        ull wp[4] = {pack2(wv.x), pack2(wv.y), pack2(wv.z), pack2(wv.w)};
#pragma unroll
        for (int j = 0; j < 4; j++) {
            fma2(acc[j][0], ap[0], wp[j]);
            fma2(acc[j][1], ap[1], wp[j]);
            fma2(acc[j][2], ap[2], wp[j]);
            fma2(acc[j][3], ap[3], wp[j]);
        }
    }
}

__global__ void zero_agg_kernel() {
    int i = blockIdx.x * blockDim.x + threadIdx.x;
    int stride = gridDim.x * blockDim.x;
    float4* p = (float4*)g_agg;
    const int n4 = NN * NF / 4;
    for (int idx = i; idx < n4; idx += stride)
        p[idx] = make_float4(0.f, 0.f, 0.f, 0.f);
}

// ---------------------------------------------------------------------------
// h = x @ lin1_w^T (no bias). 512 threads, tile 128x128, thread tile 8x4.
// ---------------------------------------------------------------------------
__global__ __launch_bounds__(512, 1)
void lin1_kernel(const float* __restrict__ x, const float* __restrict__ w, int N) {
    extern __shared__ float sm[];
    float* wt = sm;           // [k][f] 16384
    float* xT = sm + 16384;   // [k][n] 16384
    int tid = threadIdx.x;

    for (int idx = tid; idx < NF * HID; idx += 512) {
        int f = idx >> 7, k = idx & 127;
        wt[xswz(k, f)] = w[idx];
    }
    int nb = blockIdx.x * TN;
    for (int idx = tid; idx < TN * HID; idx += 512) {
        int n = idx >> 7, k = idx & 127;
        float v = (nb + n < N) ? x[(nb + n) * HID + k] : 0.f;
        xT[xswz(k, n)] = v;
    }
    __syncthreads();

    int n0 = (tid >> 5) << 3;   // warp-uniform, 0..120
    int f0 = (tid & 31) << 2;   // 0..124
    ull acc[4][4];
#pragma unroll
    for (int j = 0; j < 4; j++)
#pragma unroll
        for (int i = 0; i < 4; i++) acc[j][i] = 0ull;

    gemmP<HID>(xT, wt, n0, f0, acc);

#pragma unroll
    for (int i = 0; i < 4; i++) {
        float2 u0 = unpk2(acc[0][i]), u1 = unpk2(acc[1][i]);
        float2 u2 = unpk2(acc[2][i]), u3 = unpk2(acc[3][i]);
        int ne = nb + n0 + 2 * i;
        if (ne < N)
            *(float4*)(g_h + ne * NF + f0) = make_float4(u0.x, u1.x, u2.x, u3.x);
        if (ne + 1 < N)
            *(float4*)(g_h + (ne + 1) * NF + f0) = make_float4(u0.y, u1.y, u2.y, u3.y);
    }
}

// ---------------------------------------------------------------------------
// Fused edge kernel (persistent, 512 threads): per 128-edge tile
//   T = ssp(edge_attr @ w1^T + b1)        (GEMM1, K=50)
//   W = (T @ w2^T + b2) * envelope(C)     (GEMM2, K=128)
//   msg = h[src] * W ; red.v4(agg[dst], msg)
// ---------------------------------------------------------------------------
__global__ __launch_bounds__(512, 1)
void edge_kernel(const float* __restrict__ ea,   // [E][50]
                 const int*   __restrict__ eidx, // [2][E]
                 const float* __restrict__ ew,   // [E]
                 const float* __restrict__ w1,   // [128][50]
                 const float* __restrict__ b1,
                 const float* __restrict__ w2,   // [128][128]
                 const float* __restrict__ b2,
                 int E)
{
    extern __shared__ float sm[];
    float* w1t  = sm;                  // [50][128]  : 6400
    float* w2t  = w1t + NG * NF;       // [128][128] : 16384
    float* AT   = w2t + NF * NF;       // [50][128]  : 6400
    float* Ts   = AT + NG * TE;        // [128][128] : 16384
    float* sC   = Ts + NF * TE;        // 128
    int*   ssrc = (int*)(sC + TE);     // 128
    int*   sdst = ssrc + TE;           // 128
    float* sb1  = (float*)(sdst + TE); // 128
    float* sb2  = sb1 + NF;            // 128

    int tid = threadIdx.x;

    for (int idx = tid; idx < NF * NG; idx += 512) {
        int f = idx / NG, k = idx - f * NG;
        w1t[xswz(k, f)] = w1[idx];
    }
    for (int idx = tid; idx < NF * NF; idx += 512) {
        int f = idx >> 7, k = idx & 127;
        w2t[xswz(k, f)] = w2[idx];
    }
    if (tid < NF) { sb1[tid] = b1[tid]; sb2[tid] = b2[tid]; }
    __syncthreads();

    int e0 = (tid >> 5) << 3;   // warp-uniform, 0..120
    int f0 = (tid & 31) << 2;   // 0..124

    // per-thread packed biases (persistent across tiles)
    ull b1p[4], b2p[4];
#pragma unroll
    for (int j = 0; j < 4; j++) {
        b1p[j] = pack2(sb1[f0 + j]);
        b2p[j] = pack2(sb2[f0 + j]);
    }

    int ntiles = (E + TE - 1) / TE;
    for (int tile = blockIdx.x; tile < ntiles; tile += gridDim.x) {
        int ebase = tile * TE;

        for (int idx = tid; idx < TE * NG; idx += 512) {
            int e = idx / NG, k = idx - e * NG;
            float v = (ebase + e < E) ? ea[(ebase + e) * NG + k] : 0.f;
            AT[xswz(k, e)] = v;
        }
        if (tid < TE) {
            int e = ebase + tid;
            if (e < E) {
                float wv = ew[e];
                sC[tid] = 0.5f * (fcosf(wv * 0.31415926535897932f) + 1.0f);
                ssrc[tid] = eidx[e];
                sdst[tid] = eidx[E + e];
            } else { sC[tid] = 0.f; ssrc[tid] = 0; sdst[tid] = 0; }
        }
        __syncthreads();   // AT ready; all prev-tile Ts reads complete

        // GEMM1
        ull acc[4][4];
#pragma unroll
        for (int j = 0; j < 4; j++)
#pragma unroll
            for (int i = 0; i < 4; i++) acc[j][i] = b1p[j];
        gemmP<NG>(AT, w1t, e0, f0, acc);

        // ssp + transpose-store into Ts (conflict-free per 8-lane phase)
#pragma unroll
        for (int j = 0; j < 4; j++) {
            float2 u0 = unpk2(acc[j][0]), u1 = unpk2(acc[j][1]);
            float2 u2 = unpk2(acc[j][2]), u3 = unpk2(acc[j][3]);
            *(float4*)(Ts + xswz(f0 + j, e0)) =
                make_float4(sspf(u0.x), sspf(u0.y), sspf(u1.x), sspf(u1.y));
            *(float4*)(Ts + xswz(f0 + j, e0 + 4)) =
                make_float4(sspf(u2.x), sspf(u2.y), sspf(u3.x), sspf(u3.y));
        }
        __syncthreads();

        // GEMM2
#pragma unroll
        for (int j = 0; j < 4; j++)
#pragma unroll
            for (int i = 0; i < 4; i++) acc[j][i] = b2p[j];
        gemmP<NF>(Ts, w2t, e0, f0, acc);

        // envelope * gather h[src] * vector scatter-add agg[dst]
        // lanes of a warp cover all 128 filters of the SAME edge -> coalesced
#pragma unroll
        for (int i = 0; i < 4; i++) {
            float2 u0 = unpk2(acc[0][i]), u1 = unpk2(acc[1][i]);
            float2 u2 = unpk2(acc[2][i]), u3 = unpk2(acc[3][i]);
            int e = e0 + 2 * i;
            if (ebase + e < E) {
                float c = sC[e];
                int s = ssrc[e], d = sdst[e];
                float4 h = *(const float4*)(g_h + s * NF + f0);
                red4(g_agg + d * NF + f0,
                     u0.x * c * h.x, u1.x * c * h.y,
                     u2.x * c * h.z, u3.x * c * h.w);
            }
            if (ebase + e + 1 < E) {
                float c = sC[e + 1];
                int s = ssrc[e + 1], d = sdst[e + 1];
                float4 h = *(const float4*)(g_h + s * NF + f0);
                red4(g_agg + d * NF + f0,
                     u0.y * c * h.x, u1.y * c * h.y,
                     u2.y * c * h.z, u3.y * c * h.w);
            }
        }
    }
}

// ---------------------------------------------------------------------------
// out = ssp(agg @ lin2^T + b2) @ lin_w^T + bo. 512 threads, 8x4.
// ---------------------------------------------------------------------------
__global__ __launch_bounds__(512, 1)
void out_kernel(const float* __restrict__ w2, const float* __restrict__ b2,
                const float* __restrict__ wo, const float* __restrict__ bo,
                float* __restrict__ out, int N)
{
    extern __shared__ float sm[];
    float* w2t = sm;             // 16384
    float* wot = sm + 16384;     // 16384
    float* buf = sm + 32768;     // 16384
    float* sb2 = sm + 49152;     // 128
    float* sbo = sm + 49280;     // 128
    int tid = threadIdx.x;

    for (int idx = tid; idx < NF * NF; idx += 512) {
        int f = idx >> 7, k = idx & 127;
        w2t[xswz(k, f)] = w2[idx];
        wot[xswz(k, f)] = wo[idx];
    }
    if (tid < NF) { sb2[tid] = b2[tid]; sbo[tid] = bo[tid]; }

    int nb = blockIdx.x * TN;
    for (int idx = tid; idx < TN * NF; idx += 512) {
        int n = idx >> 7, k = idx & 127;
        float v = (nb + n < N) ? g_agg[(nb + n) * NF + k] : 0.f;
        buf[xswz(k, n)] = v;
    }
    __syncthreads();

    int n0 = (tid >> 5) << 3;
    int f0 = (tid & 31) << 2;
    ull b2p[4], bop[4];
#pragma unroll
    for (int j = 0; j < 4; j++) {
        b2p[j] = pack2(sb2[f0 + j]);
        bop[j] = pack2(sbo[f0 + j]);
    }

    ull acc[4][4];
#pragma unroll
    for (int j = 0; j < 4; j++)
#pragma unroll
        for (int i = 0; i < 4; i++) acc[j][i] = b2p[j];
    gemmP<NF>(buf, w2t, n0, f0, acc);
    __syncthreads();   // all buf reads done before overwrite

    // ssp + transpose-store h2 into buf
#pragma unroll
    for (int j = 0; j < 4; j++) {
        float2 u0 = unpk2(acc[j][0]), u1 = unpk2(acc[j][1]);
        float2 u2 = unpk2(acc[j][2]), u3 = unpk2(acc[j][3]);
        *(float4*)(buf + xswz(f0 + j, n0)) =
            make_float4(sspf(u0.x), sspf(u0.y), sspf(u1.x), sspf(u1.y));
        *(float4*)(buf + xswz(f0 + j, n0 + 4)) =
            make_float4(sspf(u2.x), sspf(u2.y), sspf(u3.x), sspf(u3.y));
    }
    __syncthreads();

#pragma unroll
    for (int j = 0; j < 4; j++)
#pragma unroll
        for (int i = 0; i < 4; i++) acc[j][i] = bop[j];
    gemmP<HID>(buf, wot, n0, f0, acc);

#pragma unroll
    for (int i = 0; i < 4; i++) {
        float2 u0 = unpk2(acc[0][i]), u1 = unpk2(acc[1][i]);
        float2 u2 = unpk2(acc[2][i]), u3 = unpk2(acc[3][i]);
        int ne = nb + n0 + 2 * i;
        if (ne < N)
            *(float4*)(out + ne * HID + f0) = make_float4(u0.x, u1.x, u2.x, u3.x);
        if (ne + 1 < N)
            *(float4*)(out + (ne + 1) * HID + f0) = make_float4(u0.y, u1.y, u2.y, u3.y);
    }
}

// ---------------------------------------------------------------------------

extern "C" void kernel_launch(void* const* d_in, const int* in_sizes, int n_in,
                              void* d_out, int out_size) {
    const float* x      = (const float*)d_in[0];
    const int*   eidx   = (const int*)  d_in[1];
    const float* ew     = (const float*)d_in[2];
    const float* ea     = (const float*)d_in[3];
    const float* mlp_w1 = (const float*)d_in[4];
    const float* mlp_b1 = (const float*)d_in[5];
    const float* mlp_w2 = (const float*)d_in[6];
    const float* mlp_b2 = (const float*)d_in[7];
    const float* lin1_w = (const float*)d_in[8];
    const float* lin2_w = (const float*)d_in[9];
    const float* lin2_b = (const float*)d_in[10];
    const float* lin_w  = (const float*)d_in[11];
    const float* lin_b  = (const float*)d_in[12];
    float* out = (float*)d_out;

    int N = in_sizes[0] / HID;
    int E = in_sizes[2];

    const int EDGE_SMEM = (NG * NF + NF * NF + NG * TE + NF * TE + 5 * 128) * 4;
    const int LIN1_SMEM = 2 * NF * NF * 4;
    const int OUT_SMEM  = (3 * NF * NF + 2 * 128) * 4;

    cudaFuncSetAttribute(edge_kernel, cudaFuncAttributeMaxDynamicSharedMemorySize, EDGE_SMEM);
    cudaFuncSetAttribute(lin1_kernel, cudaFuncAttributeMaxDynamicSharedMemorySize, LIN1_SMEM);
    cudaFuncSetAttribute(out_kernel,  cudaFuncAttributeMaxDynamicSharedMemorySize, OUT_SMEM);

    int ntile_n = (N + TN - 1) / TN;

    zero_agg_kernel<<<2048, 256>>>();
    lin1_kernel<<<ntile_n, 512, LIN1_SMEM>>>(x, lin1_w, N);
    edge_kernel<<<152, 512, EDGE_SMEM>>>(ea, eidx, ew,
                                         mlp_w1, mlp_b1, mlp_w2, mlp_b2, E);
    out_kernel<<<ntile_n, 512, OUT_SMEM>>>(lin2_w, lin2_b, lin_w, lin_b, out, N);
}

// round 6
// speedup vs baseline: 1.6550x; 1.0580x over previous
#include <cuda_runtime.h>

#define NN 40000
#define HID 128
#define NF 128
#define NG 50
#define TE 128
#define TN 128

typedef unsigned long long ull;

// device scratch (no allocations allowed)
__device__ float g_h[NN * NF];
__device__ float g_agg[NN * NF];

// XOR swizzle, bits 2-5 only: c(k) = ((k^(k>>2))&15)<<2.
//  - transpose stores (k=f0+j rows, f0=4*lane): 16B groups ((4l+j)^l)&7 are all
//    distinct within every 8-lane STS.128 phase -> conflict-free
//  - c < 64  ->  xswz(k, e+64) == xswz(k, e) + 64  (affine; +256B immediate)
//  - c multiple of 4 -> float4/ulonglong2 groups preserved
__device__ __forceinline__ int xswz(int k, int e) {
    return (k << 7) + (e ^ (((k ^ (k >> 2)) & 15) << 2));
}

// ---- packed f32x2 helpers (Blackwell FFMA2) --------------------------------
__device__ __forceinline__ ull pack2(float x) {
    ull r; unsigned xi = __float_as_uint(x);
    asm("mov.b64 %0, {%1, %1};" : "=l"(r) : "r"(xi));
    return r;
}
__device__ __forceinline__ void fma2(ull& d, ull a, ull b) {
    asm("fma.rn.f32x2 %0, %1, %2, %0;" : "+l"(d) : "l"(a), "l"(b));
}
__device__ __forceinline__ float2 unpk2(ull v) {
    unsigned lo, hi;
    asm("mov.b64 {%0, %1}, %2;" : "=r"(lo), "=r"(hi) : "l"(v));
    return make_float2(__uint_as_float(lo), __uint_as_float(hi));
}

// vector f32 reduction (sm_90+): 4 adds per instruction
__device__ __forceinline__ void red4(float* p, float a, float b, float c, float d) {
    asm volatile("red.global.add.v4.f32 [%0], {%1,%2,%3,%4};"
                 :: "l"(p), "f"(a), "f"(b), "f"(c), "f"(d) : "memory");
}

// MUFU fast exp2/log2/cos via PTX
__device__ __forceinline__ float ex2f(float x) {
    float r; asm("ex2.approx.f32 %0, %1;" : "=f"(r) : "f"(x)); return r;
}
__device__ __forceinline__ float lg2f(float x) {
    float r; asm("lg2.approx.f32 %0, %1;" : "=f"(r) : "f"(x)); return r;
}
__device__ __forceinline__ float fcosf(float x) {
    float r; asm("cos.approx.f32 %0, %1;" : "=f"(r) : "f"(x)); return r;
}

// ShiftedSoftplus (stable): max(x,0) + ln2*(lg2(1 + 2^(-|x|*log2e)) - 1)
__device__ __forceinline__ float sspf(float x) {
    float t = ex2f(-fabsf(x) * 1.4426950408889634f);
    return fmaxf(x, 0.0f) + 0.69314718055994531f * (lg2f(1.0f + t) - 1.0f);
}

// ---- packed GEMM inner loop, register-pipelined ----------------------------
// Thread tile: 8 edges {e0..e0+3, e0+64..e0+67} (4 packed pairs) x 4 filters.
// acc[j][i]: filter f0+j, edge pair i (pairs: e0+0/1, e0+2/3, e0+64/65, e0+66/67)
template<int K>
__device__ __forceinline__ void gemmP(const float* __restrict__ Asm,
                                      const float* __restrict__ Wsm,
                                      int e0, int f0, ull acc[4][4]) {
    ulonglong2 a0b, a1b; float4 wvb;
    {
        const float* ap = Asm + xswz(0, e0);
        a0b = *(const ulonglong2*)(ap);
        a1b = *(const ulonglong2*)(ap + 64);
        wvb = *(const float4*)(Wsm + xswz(0, f0));
    }
#pragma unroll 8
    for (int k = 0; k < K; k++) {
        ulonglong2 a0 = a0b, a1 = a1b; float4 wv = wvb;
        if (k + 1 < K) {   // prefetch next k while computing current
            const float* ap = Asm + xswz(k + 1, e0);
            a0b = *(const ulonglong2*)(ap);
            a1b = *(const ulonglong2*)(ap + 64);
            wvb = *(const float4*)(Wsm + xswz(k + 1, f0));
        }
        ull ap4[4] = {a0.x, a0.y, a1.x, a1.y};
        ull wp[4] = {pack2(wv.x), pack2(wv.y), pack2(wv.z), pack2(wv.w)};
#pragma unroll
        for (int j = 0; j < 4; j++) {
            fma2(acc[j][0], ap4[0], wp[j]);
            fma2(acc[j][1], ap4[1], wp[j]);
            fma2(acc[j][2], ap4[2], wp[j]);
            fma2(acc[j][3], ap4[3], wp[j]);
        }
    }
}

__global__ void zero_agg_kernel() {
    int i = blockIdx.x * blockDim.x + threadIdx.x;
    int stride = gridDim.x * blockDim.x;
    float4* p = (float4*)g_agg;
    const int n4 = NN * NF / 4;
    for (int idx = i; idx < n4; idx += stride)
        p[idx] = make_float4(0.f, 0.f, 0.f, 0.f);
}

// edge-group offsets for the 4 packed pairs
__device__ __forceinline__ int eoff(int i) { return (i < 2) ? 2 * i : 60 + 2 * i; } // 0,2,64,66

// ---------------------------------------------------------------------------
// h = x @ lin1_w^T (no bias). 512 threads, tile 128x128.
// ---------------------------------------------------------------------------
__global__ __launch_bounds__(512, 1)
void lin1_kernel(const float* __restrict__ x, const float* __restrict__ w, int N) {
    extern __shared__ float sm[];
    float* wt = sm;           // [k][f] 16384
    float* xT = sm + 16384;   // [k][n] 16384
    int tid = threadIdx.x;

    for (int idx = tid; idx < NF * HID; idx += 512) {
        int f = idx >> 7, k = idx & 127;
        wt[xswz(k, f)] = w[idx];
    }
    int nb = blockIdx.x * TN;
    for (int idx = tid; idx < TN * HID; idx += 512) {
        int n = idx >> 7, k = idx & 127;
        float v = (nb + n < N) ? x[(nb + n) * HID + k] : 0.f;
        xT[xswz(k, n)] = v;
    }
    __syncthreads();

    int n0 = (tid >> 5) << 2;   // warp-uniform, 0..60 (+64 group)
    int f0 = (tid & 31) << 2;   // 0..124
    ull acc[4][4];
#pragma unroll
    for (int j = 0; j < 4; j++)
#pragma unroll
        for (int i = 0; i < 4; i++) acc[j][i] = 0ull;

    gemmP<HID>(xT, wt, n0, f0, acc);

#pragma unroll
    for (int i = 0; i < 4; i++) {
        float2 u0 = unpk2(acc[0][i]), u1 = unpk2(acc[1][i]);
        float2 u2 = unpk2(acc[2][i]), u3 = unpk2(acc[3][i]);
        int ne = nb + n0 + eoff(i);
        if (ne < N)
            *(float4*)(g_h + ne * NF + f0) = make_float4(u0.x, u1.x, u2.x, u3.x);
        if (ne + 1 < N)
            *(float4*)(g_h + (ne + 1) * NF + f0) = make_float4(u0.y, u1.y, u2.y, u3.y);
    }
}

// ---------------------------------------------------------------------------
// Fused edge kernel (persistent, 512 threads): per 128-edge tile
//   T = ssp(edge_attr @ w1^T + b1)        (GEMM1, K=50)
//   W = (T @ w2^T + b2) * envelope(C)     (GEMM2, K=128)
//   msg = h[src] * W ; red.v4(agg[dst], msg)
// ---------------------------------------------------------------------------
__global__ __launch_bounds__(512, 1)
void edge_kernel(const float* __restrict__ ea,   // [E][50]
                 const int*   __restrict__ eidx, // [2][E]
                 const float* __restrict__ ew,   // [E]
                 const float* __restrict__ w1,   // [128][50]
                 const float* __restrict__ b1,
                 const float* __restrict__ w2,   // [128][128]
                 const float* __restrict__ b2,
                 int E)
{
    extern __shared__ float sm[];
    float* w1t  = sm;                  // [50][128]  : 6400
    float* w2t  = w1t + NG * NF;       // [128][128] : 16384
    float* AT   = w2t + NF * NF;       // [50][128]  : 6400
    float* Ts   = AT + NG * TE;        // [128][128] : 16384
    float* sC   = Ts + NF * TE;        // 128
    int*   ssrc = (int*)(sC + TE);     // 128
    int*   sdst = ssrc + TE;           // 128
    float* sb1  = (float*)(sdst + TE); // 128
    float* sb2  = sb1 + NF;            // 128

    int tid = threadIdx.x;

    for (int idx = tid; idx < NF * NG; idx += 512) {
        int f = idx / NG, k = idx - f * NG;
        w1t[xswz(k, f)] = w1[idx];
    }
    for (int idx = tid; idx < NF * NF; idx += 512) {
        int f = idx >> 7, k = idx & 127;
        w2t[xswz(k, f)] = w2[idx];
    }
    if (tid < NF) { sb1[tid] = b1[tid]; sb2[tid] = b2[tid]; }
    __syncthreads();

    int e0 = (tid >> 5) << 2;   // warp-uniform, 0..60 (+64 group)
    int f0 = (tid & 31) << 2;   // 0..124

    ull b1p[4], b2p[4];
#pragma unroll
    for (int j = 0; j < 4; j++) {
        b1p[j] = pack2(sb1[f0 + j]);
        b2p[j] = pack2(sb2[f0 + j]);
    }

    int ntiles = (E + TE - 1) / TE;
    for (int tile = blockIdx.x; tile < ntiles; tile += gridDim.x) {
        int ebase = tile * TE;

        for (int idx = tid; idx < TE * NG; idx += 512) {
            int e = idx / NG, k = idx - e * NG;
            float v = (ebase + e < E) ? ea[(ebase + e) * NG + k] : 0.f;
            AT[xswz(k, e)] = v;
        }
        if (tid < TE) {
            int e = ebase + tid;
            if (e < E) {
                float wv = ew[e];
                sC[tid] = 0.5f * (fcosf(wv * 0.31415926535897932f) + 1.0f);
                ssrc[tid] = eidx[e];
                sdst[tid] = eidx[E + e];
            } else { sC[tid] = 0.f; ssrc[tid] = 0; sdst[tid] = 0; }
        }
        __syncthreads();   // AT ready; all prev-tile Ts reads complete

        // GEMM1
        ull acc[4][4];
#pragma unroll
        for (int j = 0; j < 4; j++)
#pragma unroll
            for (int i = 0; i < 4; i++) acc[j][i] = b1p[j];
        gemmP<NG>(AT, w1t, e0, f0, acc);

        // ssp + transpose-store into Ts (conflict-free)
#pragma unroll
        for (int j = 0; j < 4; j++) {
            float2 u0 = unpk2(acc[j][0]), u1 = unpk2(acc[j][1]);
            float2 u2 = unpk2(acc[j][2]), u3 = unpk2(acc[j][3]);
            float* r = Ts + xswz(f0 + j, e0);
            *(float4*)(r) =
                make_float4(sspf(u0.x), sspf(u0.y), sspf(u1.x), sspf(u1.y));
            *(float4*)(r + 64) =
                make_float4(sspf(u2.x), sspf(u2.y), sspf(u3.x), sspf(u3.y));
        }
        __syncthreads();

        // GEMM2
#pragma unroll
        for (int j = 0; j < 4; j++)
#pragma unroll
            for (int i = 0; i < 4; i++) acc[j][i] = b2p[j];
        gemmP<NF>(Ts, w2t, e0, f0, acc);

        // envelope * gather h[src] * vector scatter-add agg[dst]
        // lanes of a warp cover all 128 filters of the SAME edge -> coalesced
#pragma unroll
        for (int i = 0; i < 4; i++) {
            float2 u0 = unpk2(acc[0][i]), u1 = unpk2(acc[1][i]);
            float2 u2 = unpk2(acc[2][i]), u3 = unpk2(acc[3][i]);
            int e = e0 + eoff(i);
            if (ebase + e < E) {
                float c = sC[e];
                int s = ssrc[e], d = sdst[e];
                float4 h = *(const float4*)(g_h + s * NF + f0);
                red4(g_agg + d * NF + f0,
                     u0.x * c * h.x, u1.x * c * h.y,
                     u2.x * c * h.z, u3.x * c * h.w);
            }
            if (ebase + e + 1 < E) {
                float c = sC[e + 1];
                int s = ssrc[e + 1], d = sdst[e + 1];
                float4 h = *(const float4*)(g_h + s * NF + f0);
                red4(g_agg + d * NF + f0,
                     u0.y * c * h.x, u1.y * c * h.y,
                     u2.y * c * h.z, u3.y * c * h.w);
            }
        }
    }
}

// ---------------------------------------------------------------------------
// out = ssp(agg @ lin2^T + b2) @ lin_w^T + bo. 512 threads.
// ---------------------------------------------------------------------------
__global__ __launch_bounds__(512, 1)
void out_kernel(const float* __restrict__ w2, const float* __restrict__ b2,
                const float* __restrict__ wo, const float* __restrict__ bo,
                float* __restrict__ out, int N)
{
    extern __shared__ float sm[];
    float* w2t = sm;             // 16384
    float* wot = sm + 16384;     // 16384
    float* buf = sm + 32768;     // 16384
    float* sb2 = sm + 49152;     // 128
    float* sbo = sm + 49280;     // 128
    int tid = threadIdx.x;

    for (int idx = tid; idx < NF * NF; idx += 512) {
        int f = idx >> 7, k = idx & 127;
        w2t[xswz(k, f)] = w2[idx];
        wot[xswz(k, f)] = wo[idx];
    }
    if (tid < NF) { sb2[tid] = b2[tid]; sbo[tid] = bo[tid]; }

    int nb = blockIdx.x * TN;
    for (int idx = tid; idx < TN * NF; idx += 512) {
        int n = idx >> 7, k = idx & 127;
        float v = (nb + n < N) ? g_agg[(nb + n) * NF + k] : 0.f;
        buf[xswz(k, n)] = v;
    }
    __syncthreads();

    int n0 = (tid >> 5) << 2;
    int f0 = (tid & 31) << 2;
    ull b2p[4], bop[4];
#pragma unroll
    for (int j = 0; j < 4; j++) {
        b2p[j] = pack2(sb2[f0 + j]);
        bop[j] = pack2(sbo[f0 + j]);
    }

    ull acc[4][4];
#pragma unroll
    for (int j = 0; j < 4; j++)
#pragma unroll
        for (int i = 0; i < 4; i++) acc[j][i] = b2p[j];
    gemmP<NF>(buf, w2t, n0, f0, acc);
    __syncthreads();   // all buf reads done before overwrite

    // ssp + transpose-store h2 into buf
#pragma unroll
    for (int j = 0; j < 4; j++) {
        float2 u0 = unpk2(acc[j][0]), u1 = unpk2(acc[j][1]);
        float2 u2 = unpk2(acc[j][2]), u3 = unpk2(acc[j][3]);
        float* r = buf + xswz(f0 + j, n0);
        *(float4*)(r) =
            make_float4(sspf(u0.x), sspf(u0.y), sspf(u1.x), sspf(u1.y));
        *(float4*)(r + 64) =
            make_float4(sspf(u2.x), sspf(u2.y), sspf(u3.x), sspf(u3.y));
    }
    __syncthreads();

#pragma unroll
    for (int j = 0; j < 4; j++)
#pragma unroll
        for (int i = 0; i < 4; i++) acc[j][i] = bop[j];
    gemmP<HID>(buf, wot, n0, f0, acc);

#pragma unroll
    for (int i = 0; i < 4; i++) {
        float2 u0 = unpk2(acc[0][i]), u1 = unpk2(acc[1][i]);
        float2 u2 = unpk2(acc[2][i]), u3 = unpk2(acc[3][i]);
        int ne = nb + n0 + eoff(i);
        if (ne < N)
            *(float4*)(out + ne * HID + f0) = make_float4(u0.x, u1.x, u2.x, u3.x);
        if (ne + 1 < N)
            *(float4*)(out + (ne + 1) * HID + f0) = make_float4(u0.y, u1.y, u2.y, u3.y);
    }
}

// ---------------------------------------------------------------------------

extern "C" void kernel_launch(void* const* d_in, const int* in_sizes, int n_in,
                              void* d_out, int out_size) {
    const float* x      = (const float*)d_in[0];
    const int*   eidx   = (const int*)  d_in[1];
    const float* ew     = (const float*)d_in[2];
    const float* ea     = (const float*)d_in[3];
    const float* mlp_w1 = (const float*)d_in[4];
    const float* mlp_b1 = (const float*)d_in[5];
    const float* mlp_w2 = (const float*)d_in[6];
    const float* mlp_b2 = (const float*)d_in[7];
    const float* lin1_w = (const float*)d_in[8];
    const float* lin2_w = (const float*)d_in[9];
    const float* lin2_b = (const float*)d_in[10];
    const float* lin_w  = (const float*)d_in[11];
    const float* lin_b  = (const float*)d_in[12];
    float* out = (float*)d_out;

    int N = in_sizes[0] / HID;
    int E = in_sizes[2];

    const int EDGE_SMEM = (NG * NF + NF * NF + NG * TE + NF * TE + 5 * 128) * 4;
    const int LIN1_SMEM = 2 * NF * NF * 4;
    const int OUT_SMEM  = (3 * NF * NF + 2 * 128) * 4;

    cudaFuncSetAttribute(edge_kernel, cudaFuncAttributeMaxDynamicSharedMemorySize, EDGE_SMEM);
    cudaFuncSetAttribute(lin1_kernel, cudaFuncAttributeMaxDynamicSharedMemorySize, LIN1_SMEM);
    cudaFuncSetAttribute(out_kernel,  cudaFuncAttributeMaxDynamicSharedMemorySize, OUT_SMEM);

    int ntile_n = (N + TN - 1) / TN;

    zero_agg_kernel<<<2048, 256>>>();
    lin1_kernel<<<ntile_n, 512, LIN1_SMEM>>>(x, lin1_w, N);
    edge_kernel<<<152, 512, EDGE_SMEM>>>(ea, eidx, ew,
                                         mlp_w1, mlp_b1, mlp_w2, mlp_b2, E);
    out_kernel<<<ntile_n, 512, OUT_SMEM>>>(lin2_w, lin2_b, lin_w, lin_b, out, N);
}

// round 9
// speedup vs baseline: 2.4653x; 1.4896x over previous
#include <cuda_runtime.h>
#include <cuda_bf16.h>
#include <cstdint>

#define NN 40000
#define HID 128
#define NF 128
#define NG 50
#define TE 128
#define TN 128

typedef unsigned long long ull;

// device scratch (no allocations allowed)
__device__ float g_h[NN * NF];
__device__ float g_agg[NN * NF];

// ===========================================================================
// scalar-path helpers (lin1 / out kernels, round-6 proven)
// ===========================================================================
__device__ __forceinline__ int xswz(int k, int e) {
    return (k << 7) + (e ^ (((k ^ (k >> 2)) & 15) << 2));
}
__device__ __forceinline__ ull pack2(float x) {
    ull r; unsigned xi = __float_as_uint(x);
    asm("mov.b64 %0, {%1, %1};" : "=l"(r) : "r"(xi));
    return r;
}
__device__ __forceinline__ void fma2(ull& d, ull a, ull b) {
    asm("fma.rn.f32x2 %0, %1, %2, %0;" : "+l"(d) : "l"(a), "l"(b));
}
__device__ __forceinline__ float2 unpk2(ull v) {
    unsigned lo, hi;
    asm("mov.b64 {%0, %1}, %2;" : "=r"(lo), "=r"(hi) : "l"(v));
    return make_float2(__uint_as_float(lo), __uint_as_float(hi));
}
__device__ __forceinline__ void red2(float* p, float a, float b) {
    asm volatile("red.global.add.v2.f32 [%0], {%1,%2};"
                 :: "l"(p), "f"(a), "f"(b) : "memory");
}
__device__ __forceinline__ float ex2f(float x) {
    float r; asm("ex2.approx.f32 %0, %1;" : "=f"(r) : "f"(x)); return r;
}
__device__ __forceinline__ float lg2f(float x) {
    float r; asm("lg2.approx.f32 %0, %1;" : "=f"(r) : "f"(x)); return r;
}
__device__ __forceinline__ float fcosf(float x) {
    float r; asm("cos.approx.f32 %0, %1;" : "=f"(r) : "f"(x)); return r;
}
__device__ __forceinline__ float sspf(float x) {
    float t = ex2f(-fabsf(x) * 1.4426950408889634f);
    return fmaxf(x, 0.0f) + 0.69314718055994531f * (lg2f(1.0f + t) - 1.0f);
}

template<int K>
__device__ __forceinline__ void gemmP(const float* __restrict__ Asm,
                                      const float* __restrict__ Wsm,
                                      int e0, int f0, ull acc[4][4]) {
    ulonglong2 a0b, a1b; float4 wvb;
    {
        const float* ap = Asm + xswz(0, e0);
        a0b = *(const ulonglong2*)(ap);
        a1b = *(const ulonglong2*)(ap + 64);
        wvb = *(const float4*)(Wsm + xswz(0, f0));
    }
#pragma unroll 8
    for (int k = 0; k < K; k++) {
        ulonglong2 a0 = a0b, a1 = a1b; float4 wv = wvb;
        if (k + 1 < K) {
            const float* ap = Asm + xswz(k + 1, e0);
            a0b = *(const ulonglong2*)(ap);
            a1b = *(const ulonglong2*)(ap + 64);
            wvb = *(const float4*)(Wsm + xswz(k + 1, f0));
        }
        ull ap4[4] = {a0.x, a0.y, a1.x, a1.y};
        ull wp[4] = {pack2(wv.x), pack2(wv.y), pack2(wv.z), pack2(wv.w)};
#pragma unroll
        for (int j = 0; j < 4; j++) {
            fma2(acc[j][0], ap4[0], wp[j]);
            fma2(acc[j][1], ap4[1], wp[j]);
            fma2(acc[j][2], ap4[2], wp[j]);
            fma2(acc[j][3], ap4[3], wp[j]);
        }
    }
}
__device__ __forceinline__ int eoff(int i) { return (i < 2) ? 2 * i : 60 + 2 * i; }

__global__ void zero_agg_kernel() {
    int i = blockIdx.x * blockDim.x + threadIdx.x;
    int stride = gridDim.x * blockDim.x;
    float4* p = (float4*)g_agg;
    const int n4 = NN * NF / 4;
    for (int idx = i; idx < n4; idx += stride)
        p[idx] = make_float4(0.f, 0.f, 0.f, 0.f);
}

// ===========================================================================
// mma.sync path helpers (portable; valid on base sm_103 target)
// ===========================================================================
__device__ __forceinline__ uint32_t smem_u32(const void* p) {
    uint32_t a;
    asm("{ .reg .u64 t; cvta.to.shared.u64 t, %1; cvt.u32.u64 %0, t; }"
        : "=r"(a) : "l"(p));
    return a;
}
__device__ __forceinline__ void ldmx4(unsigned* r, uint32_t addr) {
    asm volatile("ldmatrix.sync.aligned.m8n8.x4.shared.b16 {%0,%1,%2,%3}, [%4];"
        : "=r"(r[0]), "=r"(r[1]), "=r"(r[2]), "=r"(r[3]) : "r"(addr));
}
__device__ __forceinline__ void mma16816(float* c, const unsigned* a,
                                         unsigned b0, unsigned b1) {
    asm volatile(
        "mma.sync.aligned.m16n8k16.row.col.f32.bf16.bf16.f32 "
        "{%0,%1,%2,%3}, {%4,%5,%6,%7}, {%8,%9}, {%0,%1,%2,%3};"
        : "+f"(c[0]), "+f"(c[1]), "+f"(c[2]), "+f"(c[3])
        : "r"(a[0]), "r"(a[1]), "r"(a[2]), "r"(a[3]), "r"(b0), "r"(b1));
}
// byte offset of bf16 element (r, c) in a swizzled tile with row stride RS bytes
__device__ __forceinline__ int phy(int r, int c, int rs) {
    return r * rs + ((((c >> 3) ^ (r & 7))) << 4) + ((c & 7) << 1);
}

// smem layout (bytes) for edge kernel
#define O_W1H   0
#define O_W1L   16384
#define O_W2H   32768
#define O_W2L   65536
#define O_A1H   98304
#define O_A1L   114688
#define O_TSH   131072
#define O_TSL   163840
#define O_SC    196608
#define O_SSRC  197120
#define O_SDST  197632
#define O_SB1   198144
#define O_SB2   198656
#define EDGE_SMEM 199168

__device__ __forceinline__ void split_bf16(float v, __nv_bfloat16& h, __nv_bfloat16& lo) {
    h = __float2bfloat16_rn(v);
    lo = __float2bfloat16_rn(v - __bfloat162float(h));
}

// warp-level m16 x n64 x (16*KSTEPS) bf16-split GEMM, C += A@W^T
// A tiles (hi/lo) at aH/aL with row stride RSA; W tiles at wH/wL, stride RSW.
template<int KSTEPS, int RSA, int RSW>
__device__ __forceinline__ void warp_mma(uint32_t aH, uint32_t aL,
                                         uint32_t wH, uint32_t wL,
                                         int m0, int fbase, int lane,
                                         float C[8][4]) {
#pragma unroll
    for (int ks = 0; ks < KSTEPS; ks++) {
        unsigned Ah[4], Al[4];
        int ra = m0 + (lane & 7) + ((lane >> 3) & 1) * 8;
        int ca = 2 * ks + (lane >> 4);
        uint32_t aoff = (uint32_t)(ra * RSA + ((ca ^ (ra & 7)) << 4));
        ldmx4(Ah, aH + aoff);
        ldmx4(Al, aL + aoff);
#pragma unroll
        for (int ntp = 0; ntp < 4; ntp++) {
            int rb = fbase + 16 * ntp + (lane & 7) + (lane >> 4) * 8;
            int cb = 2 * ks + ((lane >> 3) & 1);
            uint32_t boff = (uint32_t)(rb * RSW + ((cb ^ (rb & 7)) << 4));
            unsigned Bh[4], Bl[4];
            ldmx4(Bh, wH + boff);
            ldmx4(Bl, wL + boff);
            int j = 2 * ntp;
            mma16816(C[j], Ah, Bh[0], Bh[1]);
            mma16816(C[j], Al, Bh[0], Bh[1]);
            mma16816(C[j], Ah, Bl[0], Bl[1]);
            mma16816(C[j + 1], Ah, Bh[2], Bh[3]);
            mma16816(C[j + 1], Al, Bh[2], Bh[3]);
            mma16816(C[j + 1], Ah, Bl[2], Bl[3]);
        }
    }
}

// ---------------------------------------------------------------------------
// Fused edge kernel on mma.sync tensor cores (bf16 3-product split).
// Per 128-edge tile: GEMM1 (K=64 padded) -> ssp -> GEMM2 (K=128) -> scatter.
// ---------------------------------------------------------------------------
__global__ __launch_bounds__(512, 1)
void edge_kernel(const float* __restrict__ ea,   // [E][50]
                 const int*   __restrict__ eidx, // [2][E]
                 const float* __restrict__ ew,   // [E]
                 const float* __restrict__ w1,   // [128][50]
                 const float* __restrict__ b1,
                 const float* __restrict__ w2,   // [128][128]
                 const float* __restrict__ b2,
                 int E)
{
    extern __shared__ char smem[];
    uint32_t sbase = smem_u32(smem);
    int tid = threadIdx.x;
    int w = tid >> 5, lane = tid & 31;
    int mw = w & 7;          // edge-row warp (16 rows each)
    int nw = w >> 3;         // filter-col warp (64 cols each)
    int g = lane >> 2, t = lane & 3;

    float* sC   = (float*)(smem + O_SC);
    int*   ssrc = (int*)(smem + O_SSRC);
    int*   sdst = (int*)(smem + O_SDST);
    float* sb1  = (float*)(smem + O_SB1);
    float* sb2  = (float*)(smem + O_SB2);

    // zero W1 + A1 buffers (K padding 50->64 stays zero forever)
    for (int i = tid; i < 4096; i += 512) {
        ((uint32_t*)(smem + O_W1H))[i] = 0; ((uint32_t*)(smem + O_W1L))[i] = 0;
        ((uint32_t*)(smem + O_A1H))[i] = 0; ((uint32_t*)(smem + O_A1L))[i] = 0;
    }
    __syncthreads();

    // static weights: bf16 hi/lo split into swizzled tiles
    for (int idx = tid; idx < NF * NG; idx += 512) {
        int f = idx / NG, k = idx - f * NG;
        __nv_bfloat16 h, lo; split_bf16(w1[idx], h, lo);
        int o = phy(f, k, 128);
        *(__nv_bfloat16*)(smem + O_W1H + o) = h;
        *(__nv_bfloat16*)(smem + O_W1L + o) = lo;
    }
    for (int idx = tid; idx < NF * NF; idx += 512) {
        int f = idx >> 7, k = idx & 127;
        __nv_bfloat16 h, lo; split_bf16(w2[idx], h, lo);
        int o = phy(f, k, 256);
        *(__nv_bfloat16*)(smem + O_W2H + o) = h;
        *(__nv_bfloat16*)(smem + O_W2L + o) = lo;
    }
    if (tid < NF) { sb1[tid] = b1[tid]; sb2[tid] = b2[tid]; }

    const uint32_t A1H = sbase + O_A1H, A1L = sbase + O_A1L;
    const uint32_t W1H = sbase + O_W1H, W1L = sbase + O_W1L;
    const uint32_t W2H = sbase + O_W2H, W2L = sbase + O_W2L;
    const uint32_t TSH = sbase + O_TSH, TSL = sbase + O_TSL;

    int e0r = 16 * mw + g;       // this thread's first edge row
    int e1r = e0r + 8;           // second edge row
    int ntiles = (E + TE - 1) / TE;

    for (int tile = blockIdx.x; tile < ntiles; tile += gridDim.x) {
        int ebase = tile * TE;

        __syncthreads();   // prior tile's readers of A1/sC done

        // ---- stage A1 (edge_attr tile, bf16 split, swizzled) ----
        for (int idx = tid; idx < TE * NG; idx += 512) {
            int e = idx / NG, k = idx - e * NG;
            float v = (ebase + e < E) ? ea[(ebase + e) * NG + k] : 0.f;
            __nv_bfloat16 h, lo; split_bf16(v, h, lo);
            int o = phy(e, k, 128);
            *(__nv_bfloat16*)(smem + O_A1H + o) = h;
            *(__nv_bfloat16*)(smem + O_A1L + o) = lo;
        }
        if (tid < TE) {
            int e = ebase + tid;
            if (e < E) {
                sC[tid] = 0.5f * (fcosf(ew[e] * 0.31415926535897932f) + 1.0f);
                ssrc[tid] = eidx[e];
                sdst[tid] = eidx[E + e];
            } else { sC[tid] = 0.f; ssrc[tid] = 0; sdst[tid] = 0; }
        }
        __syncthreads();

        // ---- GEMM1: C = A1 @ W1^T  (K=64: 4 k-steps) ----
        float C[8][4];
#pragma unroll
        for (int j = 0; j < 8; j++)
#pragma unroll
            for (int q = 0; q < 4; q++) C[j][q] = 0.f;
        warp_mma<4, 128, 128>(A1H, A1L, W1H, W1L, 16 * mw, 64 * nw, lane, C);

        // ---- epilogue1: bias + ssp -> split -> Ts ----
#pragma unroll
        for (int j = 0; j < 8; j++) {
            int f = 64 * nw + 8 * j + 2 * t;
            float bb0 = sb1[f], bb1 = sb1[f + 1];
            float v00 = sspf(C[j][0] + bb0), v01 = sspf(C[j][1] + bb1);
            float v10 = sspf(C[j][2] + bb0), v11 = sspf(C[j][3] + bb1);
            __nv_bfloat16 h0, l0, h1, l1;
            __nv_bfloat162 hh, ll;
            split_bf16(v00, h0, l0); split_bf16(v01, h1, l1);
            hh.x = h0; hh.y = h1; ll.x = l0; ll.y = l1;
            int o0 = phy(e0r, f, 256);
            *(__nv_bfloat162*)(smem + O_TSH + o0) = hh;
            *(__nv_bfloat162*)(smem + O_TSL + o0) = ll;
            split_bf16(v10, h0, l0); split_bf16(v11, h1, l1);
            hh.x = h0; hh.y = h1; ll.x = l0; ll.y = l1;
            int o1 = phy(e1r, f, 256);
            *(__nv_bfloat162*)(smem + O_TSH + o1) = hh;
            *(__nv_bfloat162*)(smem + O_TSL + o1) = ll;
        }
        __syncthreads();

        // ---- GEMM2: C = Ts @ W2^T (K=128: 8 k-steps) ----
#pragma unroll
        for (int j = 0; j < 8; j++)
#pragma unroll
            for (int q = 0; q < 4; q++) C[j][q] = 0.f;
        warp_mma<8, 256, 256>(TSH, TSL, W2H, W2L, 16 * mw, 64 * nw, lane, C);

        // ---- epilogue2: (C + b2) * env * h[src] -> red.v2 agg[dst] ----
        {
            int ge0 = ebase + e0r, ge1 = ebase + e1r;
            float c0 = sC[e0r], c1 = sC[e1r];
            int s0 = ssrc[e0r], d0 = sdst[e0r];
            int s1 = ssrc[e1r], d1 = sdst[e1r];
#pragma unroll
            for (int j = 0; j < 8; j++) {
                int f = 64 * nw + 8 * j + 2 * t;
                float bb0 = sb2[f], bb1 = sb2[f + 1];
                if (ge0 < E) {
                    float2 h = *(const float2*)(g_h + s0 * NF + f);
                    red2(g_agg + d0 * NF + f,
                         (C[j][0] + bb0) * c0 * h.x,
                         (C[j][1] + bb1) * c0 * h.y);
                }
                if (ge1 < E) {
                    float2 h = *(const float2*)(g_h + s1 * NF + f);
                    red2(g_agg + d1 * NF + f,
                         (C[j][2] + bb0) * c1 * h.x,
                         (C[j][3] + bb1) * c1 * h.y);
                }
            }
        }
    }
}

// ---------------------------------------------------------------------------
// h = x @ lin1_w^T (no bias). 512 threads, scalar FFMA2 path.
// ---------------------------------------------------------------------------
__global__ __launch_bounds__(512, 1)
void lin1_kernel(const float* __restrict__ x, const float* __restrict__ w, int N) {
    extern __shared__ float sm[];
    float* wt = sm;
    float* xT = sm + 16384;
    int tid = threadIdx.x;

    for (int idx = tid; idx < NF * HID; idx += 512) {
        int f = idx >> 7, k = idx & 127;
        wt[xswz(k, f)] = w[idx];
    }
    int nb = blockIdx.x * TN;
    for (int idx = tid; idx < TN * HID; idx += 512) {
        int n = idx >> 7, k = idx & 127;
        float v = (nb + n < N) ? x[(nb + n) * HID + k] : 0.f;
        xT[xswz(k, n)] = v;
    }
    __syncthreads();

    int n0 = (tid >> 5) << 2;
    int f0 = (tid & 31) << 2;
    ull acc[4][4];
#pragma unroll
    for (int j = 0; j < 4; j++)
#pragma unroll
        for (int i = 0; i < 4; i++) acc[j][i] = 0ull;

    gemmP<HID>(xT, wt, n0, f0, acc);

#pragma unroll
    for (int i = 0; i < 4; i++) {
        float2 u0 = unpk2(acc[0][i]), u1 = unpk2(acc[1][i]);
        float2 u2 = unpk2(acc[2][i]), u3 = unpk2(acc[3][i]);
        int ne = nb + n0 + eoff(i);
        if (ne < N)
            *(float4*)(g_h + ne * NF + f0) = make_float4(u0.x, u1.x, u2.x, u3.x);
        if (ne + 1 < N)
            *(float4*)(g_h + (ne + 1) * NF + f0) = make_float4(u0.y, u1.y, u2.y, u3.y);
    }
}

// ---------------------------------------------------------------------------
// out = ssp(agg @ lin2^T + b2) @ lin_w^T + bo. 512 threads, scalar path.
// ---------------------------------------------------------------------------
__global__ __launch_bounds__(512, 1)
void out_kernel(const float* __restrict__ w2, const float* __restrict__ b2,
                const float* __restrict__ wo, const float* __restrict__ bo,
                float* __restrict__ out, int N)
{
    extern __shared__ float sm[];
    float* w2t = sm;
    float* wot = sm + 16384;
    float* buf = sm + 32768;
    float* sb2 = sm + 49152;
    float* sbo = sm + 49280;
    int tid = threadIdx.x;

    for (int idx = tid; idx < NF * NF; idx += 512) {
        int f = idx >> 7, k = idx & 127;
        w2t[xswz(k, f)] = w2[idx];
        wot[xswz(k, f)] = wo[idx];
    }
    if (tid < NF) { sb2[tid] = b2[tid]; sbo[tid] = bo[tid]; }

    int nb = blockIdx.x * TN;
    for (int idx = tid; idx < TN * NF; idx += 512) {
        int n = idx >> 7, k = idx & 127;
        float v = (nb + n < N) ? g_agg[(nb + n) * NF + k] : 0.f;
        buf[xswz(k, n)] = v;
    }
    __syncthreads();

    int n0 = (tid >> 5) << 2;
    int f0 = (tid & 31) << 2;
    ull b2p[4], bop[4];
#pragma unroll
    for (int j = 0; j < 4; j++) {
        b2p[j] = pack2(sb2[f0 + j]);
        bop[j] = pack2(sbo[f0 + j]);
    }

    ull acc[4][4];
#pragma unroll
    for (int j = 0; j < 4; j++)
#pragma unroll
        for (int i = 0; i < 4; i++) acc[j][i] = b2p[j];
    gemmP<NF>(buf, w2t, n0, f0, acc);
    __syncthreads();

#pragma unroll
    for (int j = 0; j < 4; j++) {
        float2 u0 = unpk2(acc[j][0]), u1 = unpk2(acc[j][1]);
        float2 u2 = unpk2(acc[j][2]), u3 = unpk2(acc[j][3]);
        float* r = buf + xswz(f0 + j, n0);
        *(float4*)(r) =
            make_float4(sspf(u0.x), sspf(u0.y), sspf(u1.x), sspf(u1.y));
        *(float4*)(r + 64) =
            make_float4(sspf(u2.x), sspf(u2.y), sspf(u3.x), sspf(u3.y));
    }
    __syncthreads();

#pragma unroll
    for (int j = 0; j < 4; j++)
#pragma unroll
        for (int i = 0; i < 4; i++) acc[j][i] = bop[j];
    gemmP<HID>(buf, wot, n0, f0, acc);

#pragma unroll
    for (int i = 0; i < 4; i++) {
        float2 u0 = unpk2(acc[0][i]), u1 = unpk2(acc[1][i]);
        float2 u2 = unpk2(acc[2][i]), u3 = unpk2(acc[3][i]);
        int ne = nb + n0 + eoff(i);
        if (ne < N)
            *(float4*)(out + ne * HID + f0) = make_float4(u0.x, u1.x, u2.x, u3.x);
        if (ne + 1 < N)
            *(float4*)(out + (ne + 1) * HID + f0) = make_float4(u0.y, u1.y, u2.y, u3.y);
    }
}

// ---------------------------------------------------------------------------

extern "C" void kernel_launch(void* const* d_in, const int* in_sizes, int n_in,
                              void* d_out, int out_size) {
    const float* x      = (const float*)d_in[0];
    const int*   eidx   = (const int*)  d_in[1];
    const float* ew     = (const float*)d_in[2];
    const float* ea     = (const float*)d_in[3];
    const float* mlp_w1 = (const float*)d_in[4];
    const float* mlp_b1 = (const float*)d_in[5];
    const float* mlp_w2 = (const float*)d_in[6];
    const float* mlp_b2 = (const float*)d_in[7];
    const float* lin1_w = (const float*)d_in[8];
    const float* lin2_w = (const float*)d_in[9];
    const float* lin2_b = (const float*)d_in[10];
    const float* lin_w  = (const float*)d_in[11];
    const float* lin_b  = (const float*)d_in[12];
    float* out = (float*)d_out;

    int N = in_sizes[0] / HID;
    int E = in_sizes[2];

    const int LIN1_SMEM = 2 * NF * NF * 4;
    const int OUT_SMEM  = (3 * NF * NF + 2 * 128) * 4;

    cudaFuncSetAttribute(edge_kernel, cudaFuncAttributeMaxDynamicSharedMemorySize, EDGE_SMEM);
    cudaFuncSetAttribute(lin1_kernel, cudaFuncAttributeMaxDynamicSharedMemorySize, LIN1_SMEM);
    cudaFuncSetAttribute(out_kernel,  cudaFuncAttributeMaxDynamicSharedMemorySize, OUT_SMEM);

    int ntile_n = (N + TN - 1) / TN;

    zero_agg_kernel<<<2048, 256>>>();
    lin1_kernel<<<ntile_n, 512, LIN1_SMEM>>>(x, lin1_w, N);
    edge_kernel<<<152, 512, EDGE_SMEM>>>(ea, eidx, ew,
                                         mlp_w1, mlp_b1, mlp_w2, mlp_b2, E);
    out_kernel<<<ntile_n, 512, OUT_SMEM>>>(lin2_w, lin2_b, lin_w, lin_b, out, N);
}

// round 10
// speedup vs baseline: 2.8098x; 1.1398x over previous
#include <cuda_runtime.h>
#include <cuda_bf16.h>
#include <cstdint>

#define NN 40000
#define HID 128
#define NF 128
#define NG 50
#define TE 128
#define TN 128

typedef unsigned long long ull;

// device scratch (no allocations allowed)
__device__ float g_h[NN * NF];
__device__ float g_agg[NN * NF];

// ===========================================================================
// common helpers
// ===========================================================================
__device__ __forceinline__ void red2(float* p, float a, float b) {
    asm volatile("red.global.add.v2.f32 [%0], {%1,%2};"
                 :: "l"(p), "f"(a), "f"(b) : "memory");
}
__device__ __forceinline__ float ex2f(float x) {
    float r; asm("ex2.approx.f32 %0, %1;" : "=f"(r) : "f"(x)); return r;
}
__device__ __forceinline__ float lg2f(float x) {
    float r; asm("lg2.approx.f32 %0, %1;" : "=f"(r) : "f"(x)); return r;
}
__device__ __forceinline__ float fcosf(float x) {
    float r; asm("cos.approx.f32 %0, %1;" : "=f"(r) : "f"(x)); return r;
}
__device__ __forceinline__ float sspf(float x) {
    float t = ex2f(-fabsf(x) * 1.4426950408889634f);
    return fmaxf(x, 0.0f) + 0.69314718055994531f * (lg2f(1.0f + t) - 1.0f);
}

__global__ void zero_agg_kernel() {
    int i = blockIdx.x * blockDim.x + threadIdx.x;
    int stride = gridDim.x * blockDim.x;
    float4* p = (float4*)g_agg;
    const int n4 = NN * NF / 4;
    for (int idx = i; idx < n4; idx += stride)
        p[idx] = make_float4(0.f, 0.f, 0.f, 0.f);
}

// ===========================================================================
// mma.sync helpers (portable; valid on base sm_103 target)
// ===========================================================================
__device__ __forceinline__ uint32_t smem_u32(const void* p) {
    uint32_t a;
    asm("{ .reg .u64 t; cvta.to.shared.u64 t, %1; cvt.u32.u64 %0, t; }"
        : "=r"(a) : "l"(p));
    return a;
}
__device__ __forceinline__ void ldmx4(unsigned* r, uint32_t addr) {
    asm volatile("ldmatrix.sync.aligned.m8n8.x4.shared.b16 {%0,%1,%2,%3}, [%4];"
        : "=r"(r[0]), "=r"(r[1]), "=r"(r[2]), "=r"(r[3]) : "r"(addr));
}
__device__ __forceinline__ void mma16816(float* c, const unsigned* a,
                                         unsigned b0, unsigned b1) {
    asm volatile(
        "mma.sync.aligned.m16n8k16.row.col.f32.bf16.bf16.f32 "
        "{%0,%1,%2,%3}, {%4,%5,%6,%7}, {%8,%9}, {%0,%1,%2,%3};"
        : "+f"(c[0]), "+f"(c[1]), "+f"(c[2]), "+f"(c[3])
        : "r"(a[0]), "r"(a[1]), "r"(a[2]), "r"(a[3]), "r"(b0), "r"(b1));
}
// byte offset of bf16 element (r, c) in a swizzled tile with row stride rs bytes
__device__ __forceinline__ int phy(int r, int c, int rs) {
    return r * rs + ((((c >> 3) ^ (r & 7))) << 4) + ((c & 7) << 1);
}
__device__ __forceinline__ void split_bf16(float v, __nv_bfloat16& h, __nv_bfloat16& lo) {
    h = __float2bfloat16_rn(v);
    lo = __float2bfloat16_rn(v - __bfloat162float(h));
}

// warp-level m16 x n64 x (16*KSTEPS) bf16-split GEMM, C += A@W^T
template<int KSTEPS, int RSA, int RSW>
__device__ __forceinline__ void warp_mma(uint32_t aH, uint32_t aL,
                                         uint32_t wH, uint32_t wL,
                                         int m0, int fbase, int lane,
                                         float C[8][4]) {
#pragma unroll
    for (int ks = 0; ks < KSTEPS; ks++) {
        unsigned Ah[4], Al[4];
        int ra = m0 + (lane & 7) + ((lane >> 3) & 1) * 8;
        int ca = 2 * ks + (lane >> 4);
        uint32_t aoff = (uint32_t)(ra * RSA + ((ca ^ (ra & 7)) << 4));
        ldmx4(Ah, aH + aoff);
        ldmx4(Al, aL + aoff);
#pragma unroll
        for (int ntp = 0; ntp < 4; ntp++) {
            int rb = fbase + 16 * ntp + (lane & 7) + (lane >> 4) * 8;
            int cb = 2 * ks + ((lane >> 3) & 1);
            uint32_t boff = (uint32_t)(rb * RSW + ((cb ^ (rb & 7)) << 4));
            unsigned Bh[4], Bl[4];
            ldmx4(Bh, wH + boff);
            ldmx4(Bl, wL + boff);
            int j = 2 * ntp;
            mma16816(C[j], Ah, Bh[0], Bh[1]);
            mma16816(C[j], Al, Bh[0], Bh[1]);
            mma16816(C[j], Ah, Bl[0], Bl[1]);
            mma16816(C[j + 1], Ah, Bh[2], Bh[3]);
            mma16816(C[j + 1], Al, Bh[2], Bh[3]);
            mma16816(C[j + 1], Ah, Bl[2], Bl[3]);
        }
    }
}

// ===========================================================================
// edge kernel smem layout (bytes)
// ===========================================================================
#define O_W1H   0
#define O_W1L   16384
#define O_W2H   32768
#define O_W2L   65536
#define O_A1H   98304
#define O_A1L   114688
#define O_TSH   131072
#define O_TSL   163840
#define O_SC    196608
#define O_SSRC  197120
#define O_SDST  197632
#define O_SB1   198144
#define O_SB2   198656
#define EDGE_SMEM 199168

// ---------------------------------------------------------------------------
// Fused edge kernel on mma.sync tensor cores (bf16 3-product split).
// ---------------------------------------------------------------------------
__global__ __launch_bounds__(512, 1)
void edge_kernel(const float* __restrict__ ea,   // [E][50]
                 const int*   __restrict__ eidx, // [2][E]
                 const float* __restrict__ ew,   // [E]
                 const float* __restrict__ w1,   // [128][50]
                 const float* __restrict__ b1,
                 const float* __restrict__ w2,   // [128][128]
                 const float* __restrict__ b2,
                 int E)
{
    extern __shared__ char smem[];
    uint32_t sbase = smem_u32(smem);
    int tid = threadIdx.x;
    int w = tid >> 5, lane = tid & 31;
    int mw = w & 7;          // edge-row warp (16 rows each)
    int nw = w >> 3;         // filter-col warp (64 cols each)
    int g = lane >> 2, t = lane & 3;

    float* sC   = (float*)(smem + O_SC);
    int*   ssrc = (int*)(smem + O_SSRC);
    int*   sdst = (int*)(smem + O_SDST);
    float* sb1  = (float*)(smem + O_SB1);
    float* sb2  = (float*)(smem + O_SB2);

    // zero W1 + A1 buffers (K padding 50->64 stays zero forever)
    for (int i = tid; i < 4096; i += 512) {
        ((uint32_t*)(smem + O_W1H))[i] = 0; ((uint32_t*)(smem + O_W1L))[i] = 0;
        ((uint32_t*)(smem + O_A1H))[i] = 0; ((uint32_t*)(smem + O_A1L))[i] = 0;
    }
    __syncthreads();

    for (int idx = tid; idx < NF * NG; idx += 512) {
        int f = idx / NG, k = idx - f * NG;
        __nv_bfloat16 h, lo; split_bf16(w1[idx], h, lo);
        int o = phy(f, k, 128);
        *(__nv_bfloat16*)(smem + O_W1H + o) = h;
        *(__nv_bfloat16*)(smem + O_W1L + o) = lo;
    }
    for (int idx = tid; idx < NF * NF; idx += 512) {
        int f = idx >> 7, k = idx & 127;
        __nv_bfloat16 h, lo; split_bf16(w2[idx], h, lo);
        int o = phy(f, k, 256);
        *(__nv_bfloat16*)(smem + O_W2H + o) = h;
        *(__nv_bfloat16*)(smem + O_W2L + o) = lo;
    }
    if (tid < NF) { sb1[tid] = b1[tid]; sb2[tid] = b2[tid]; }

    const uint32_t A1H = sbase + O_A1H, A1L = sbase + O_A1L;
    const uint32_t W1H = sbase + O_W1H, W1L = sbase + O_W1L;
    const uint32_t W2H = sbase + O_W2H, W2L = sbase + O_W2L;
    const uint32_t TSH = sbase + O_TSH, TSL = sbase + O_TSL;

    int e0r = 16 * mw + g;
    int e1r = e0r + 8;
    int ntiles = (E + TE - 1) / TE;

    for (int tile = blockIdx.x; tile < ntiles; tile += gridDim.x) {
        int ebase = tile * TE;

        __syncthreads();   // prior tile's readers of A1/sC done

        for (int idx = tid; idx < TE * NG; idx += 512) {
            int e = idx / NG, k = idx - e * NG;
            float v = (ebase + e < E) ? ea[(ebase + e) * NG + k] : 0.f;
            __nv_bfloat16 h, lo; split_bf16(v, h, lo);
            int o = phy(e, k, 128);
            *(__nv_bfloat16*)(smem + O_A1H + o) = h;
            *(__nv_bfloat16*)(smem + O_A1L + o) = lo;
        }
        if (tid < TE) {
            int e = ebase + tid;
            if (e < E) {
                sC[tid] = 0.5f * (fcosf(ew[e] * 0.31415926535897932f) + 1.0f);
                ssrc[tid] = eidx[e];
                sdst[tid] = eidx[E + e];
            } else { sC[tid] = 0.f; ssrc[tid] = 0; sdst[tid] = 0; }
        }
        __syncthreads();

        // GEMM1 (K=64 padded: 4 k-steps)
        float C[8][4];
#pragma unroll
        for (int j = 0; j < 8; j++)
#pragma unroll
            for (int q = 0; q < 4; q++) C[j][q] = 0.f;
        warp_mma<4, 128, 128>(A1H, A1L, W1H, W1L, 16 * mw, 64 * nw, lane, C);

        // epilogue1: bias + ssp -> split -> Ts
#pragma unroll
        for (int j = 0; j < 8; j++) {
            int f = 64 * nw + 8 * j + 2 * t;
            float bb0 = sb1[f], bb1 = sb1[f + 1];
            float v00 = sspf(C[j][0] + bb0), v01 = sspf(C[j][1] + bb1);
            float v10 = sspf(C[j][2] + bb0), v11 = sspf(C[j][3] + bb1);
            __nv_bfloat16 h0, l0, h1, l1;
            __nv_bfloat162 hh, ll;
            split_bf16(v00, h0, l0); split_bf16(v01, h1, l1);
            hh.x = h0; hh.y = h1; ll.x = l0; ll.y = l1;
            int o0 = phy(e0r, f, 256);
            *(__nv_bfloat162*)(smem + O_TSH + o0) = hh;
            *(__nv_bfloat162*)(smem + O_TSL + o0) = ll;
            split_bf16(v10, h0, l0); split_bf16(v11, h1, l1);
            hh.x = h0; hh.y = h1; ll.x = l0; ll.y = l1;
            int o1 = phy(e1r, f, 256);
            *(__nv_bfloat162*)(smem + O_TSH + o1) = hh;
            *(__nv_bfloat162*)(smem + O_TSL + o1) = ll;
        }
        __syncthreads();

        // GEMM2 (K=128: 8 k-steps)
#pragma unroll
        for (int j = 0; j < 8; j++)
#pragma unroll
            for (int q = 0; q < 4; q++) C[j][q] = 0.f;
        warp_mma<8, 256, 256>(TSH, TSL, W2H, W2L, 16 * mw, 64 * nw, lane, C);

        // epilogue2: (C + b2) * env * h[src] -> red.v2 agg[dst]
        {
            int ge0 = ebase + e0r, ge1 = ebase + e1r;
            float c0 = sC[e0r], c1 = sC[e1r];
            int s0 = ssrc[e0r], d0 = sdst[e0r];
            int s1 = ssrc[e1r], d1 = sdst[e1r];
#pragma unroll
            for (int j = 0; j < 8; j++) {
                int f = 64 * nw + 8 * j + 2 * t;
                float bb0 = sb2[f], bb1 = sb2[f + 1];
                if (ge0 < E) {
                    float2 h = *(const float2*)(g_h + s0 * NF + f);
                    red2(g_agg + d0 * NF + f,
                         (C[j][0] + bb0) * c0 * h.x,
                         (C[j][1] + bb1) * c0 * h.y);
                }
                if (ge1 < E) {
                    float2 h = *(const float2*)(g_h + s1 * NF + f);
                    red2(g_agg + d1 * NF + f,
                         (C[j][2] + bb0) * c1 * h.x,
                         (C[j][3] + bb1) * c1 * h.y);
                }
            }
        }
    }
}

// ===========================================================================
// lin1 on mma.sync: h = x @ lin1_w^T (no bias). 512 threads, 128x128 tiles.
// smem: WH 0, WL 32768, XH 65536, XL 98304  (131072 bytes)
// ===========================================================================
#define LIN1_SMEM 131072

__global__ __launch_bounds__(512, 1)
void lin1_kernel(const float* __restrict__ x, const float* __restrict__ w, int N) {
    extern __shared__ char smem[];
    uint32_t sbase = smem_u32(smem);
    int tid = threadIdx.x;
    int wp = tid >> 5, lane = tid & 31;
    int mw = wp & 7, nw = wp >> 3;
    int g = lane >> 2, t = lane & 3;

    for (int idx = tid; idx < NF * HID; idx += 512) {
        int f = idx >> 7, k = idx & 127;
        __nv_bfloat16 h, lo; split_bf16(w[idx], h, lo);
        int o = phy(f, k, 256);
        *(__nv_bfloat16*)(smem + 0 + o) = h;
        *(__nv_bfloat16*)(smem + 32768 + o) = lo;
    }
    int nb = blockIdx.x * TN;
    for (int idx = tid; idx < TN * HID; idx += 512) {
        int n = idx >> 7, k = idx & 127;
        float v = (nb + n < N) ? x[(nb + n) * HID + k] : 0.f;
        __nv_bfloat16 h, lo; split_bf16(v, h, lo);
        int o = phy(n, k, 256);
        *(__nv_bfloat16*)(smem + 65536 + o) = h;
        *(__nv_bfloat16*)(smem + 98304 + o) = lo;
    }
    __syncthreads();

    float C[8][4];
#pragma unroll
    for (int j = 0; j < 8; j++)
#pragma unroll
        for (int q = 0; q < 4; q++) C[j][q] = 0.f;
    warp_mma<8, 256, 256>(sbase + 65536, sbase + 98304,
                          sbase + 0, sbase + 32768,
                          16 * mw, 64 * nw, lane, C);

    int r0 = nb + 16 * mw + g, r1 = r0 + 8;
#pragma unroll
    for (int j = 0; j < 8; j++) {
        int f = 64 * nw + 8 * j + 2 * t;
        if (r0 < N) *(float2*)(g_h + r0 * NF + f) = make_float2(C[j][0], C[j][1]);
        if (r1 < N) *(float2*)(g_h + r1 * NF + f) = make_float2(C[j][2], C[j][3]);
    }
}

// ===========================================================================
// out on mma.sync: out = ssp(agg @ lin2^T + b2) @ lin_w^T + bo.
// smem: W2H 0, W2L 32768, WOH 65536, WOL 98304, AH 131072, AL 163840,
//       sb2 196608, sbo 197120   (197632 bytes)
// ===========================================================================
#define OUT_SMEM 197632

__global__ __launch_bounds__(512, 1)
void out_kernel(const float* __restrict__ w2, const float* __restrict__ b2,
                const float* __restrict__ wo, const float* __restrict__ bo,
                float* __restrict__ out, int N)
{
    extern __shared__ char smem[];
    uint32_t sbase = smem_u32(smem);
    int tid = threadIdx.x;
    int wp = tid >> 5, lane = tid & 31;
    int mw = wp & 7, nw = wp >> 3;
    int g = lane >> 2, t = lane & 3;

    float* sb2 = (float*)(smem + 196608);
    float* sbo = (float*)(smem + 197120);

    for (int idx = tid; idx < NF * NF; idx += 512) {
        int f = idx >> 7, k = idx & 127;
        int o = phy(f, k, 256);
        __nv_bfloat16 h, lo;
        split_bf16(w2[idx], h, lo);
        *(__nv_bfloat16*)(smem + 0 + o) = h;
        *(__nv_bfloat16*)(smem + 32768 + o) = lo;
        split_bf16(wo[idx], h, lo);
        *(__nv_bfloat16*)(smem + 65536 + o) = h;
        *(__nv_bfloat16*)(smem + 98304 + o) = lo;
    }
    if (tid < NF) { sb2[tid] = b2[tid]; sbo[tid] = bo[tid]; }

    int nb = blockIdx.x * TN;
    for (int idx = tid; idx < TN * NF; idx += 512) {
        int n = idx >> 7, k = idx & 127;
        float v = (nb + n < N) ? g_agg[(nb + n) * NF + k] : 0.f;
        __nv_bfloat16 h, lo; split_bf16(v, h, lo);
        int o = phy(n, k, 256);
        *(__nv_bfloat16*)(smem + 131072 + o) = h;
        *(__nv_bfloat16*)(smem + 163840 + o) = lo;
    }
    __syncthreads();

    // GEMM1: C = agg @ lin2^T
    float C[8][4];
#pragma unroll
    for (int j = 0; j < 8; j++)
#pragma unroll
        for (int q = 0; q < 4; q++) C[j][q] = 0.f;
    warp_mma<8, 256, 256>(sbase + 131072, sbase + 163840,
                          sbase + 0, sbase + 32768,
                          16 * mw, 64 * nw, lane, C);
    __syncthreads();   // all A reads done before overwrite

    // epilogue: bias + ssp -> split -> back into A buffers (as h2)
    int e0r = 16 * mw + g, e1r = e0r + 8;
#pragma unroll
    for (int j = 0; j < 8; j++) {
        int f = 64 * nw + 8 * j + 2 * t;
        float bb0 = sb2[f], bb1 = sb2[f + 1];
        float v00 = sspf(C[j][0] + bb0), v01 = sspf(C[j][1] + bb1);
        float v10 = sspf(C[j][2] + bb0), v11 = sspf(C[j][3] + bb1);
        __nv_bfloat16 h0, l0, h1, l1;
        __nv_bfloat162 hh, ll;
        split_bf16(v00, h0, l0); split_bf16(v01, h1, l1);
        hh.x = h0; hh.y = h1; ll.x = l0; ll.y = l1;
        int o0 = phy(e0r, f, 256);
        *(__nv_bfloat162*)(smem + 131072 + o0) = hh;
        *(__nv_bfloat162*)(smem + 163840 + o0) = ll;
        split_bf16(v10, h0, l0); split_bf16(v11, h1, l1);
        hh.x = h0; hh.y = h1; ll.x = l0; ll.y = l1;
        int o1 = phy(e1r, f, 256);
        *(__nv_bfloat162*)(smem + 131072 + o1) = hh;
        *(__nv_bfloat162*)(smem + 163840 + o1) = ll;
    }
    __syncthreads();

    // GEMM2: C = h2 @ lin_w^T
#pragma unroll
    for (int j = 0; j < 8; j++)
#pragma unroll
        for (int q = 0; q < 4; q++) C[j][q] = 0.f;
    warp_mma<8, 256, 256>(sbase + 131072, sbase + 163840,
                          sbase + 65536, sbase + 98304,
                          16 * mw, 64 * nw, lane, C);

    int r0 = nb + e0r, r1 = nb + e1r;
#pragma unroll
    for (int j = 0; j < 8; j++) {
        int f = 64 * nw + 8 * j + 2 * t;
        float bb0 = sbo[f], bb1 = sbo[f + 1];
        if (r0 < N)
            *(float2*)(out + r0 * HID + f) = make_float2(C[j][0] + bb0, C[j][1] + bb1);
        if (r1 < N)
            *(float2*)(out + r1 * HID + f) = make_float2(C[j][2] + bb0, C[j][3] + bb1);
    }
}

// ---------------------------------------------------------------------------

extern "C" void kernel_launch(void* const* d_in, const int* in_sizes, int n_in,
                              void* d_out, int out_size) {
    const float* x      = (const float*)d_in[0];
    const int*   eidx   = (const int*)  d_in[1];
    const float* ew     = (const float*)d_in[2];
    const float* ea     = (const float*)d_in[3];
    const float* mlp_w1 = (const float*)d_in[4];
    const float* mlp_b1 = (const float*)d_in[5];
    const float* mlp_w2 = (const float*)d_in[6];
    const float* mlp_b2 = (const float*)d_in[7];
    const float* lin1_w = (const float*)d_in[8];
    const float* lin2_w = (const float*)d_in[9];
    const float* lin2_b = (const float*)d_in[10];
    const float* lin_w  = (const float*)d_in[11];
    const float* lin_b  = (const float*)d_in[12];
    float* out = (float*)d_out;

    int N = in_sizes[0] / HID;
    int E = in_sizes[2];

    cudaFuncSetAttribute(edge_kernel, cudaFuncAttributeMaxDynamicSharedMemorySize, EDGE_SMEM);
    cudaFuncSetAttribute(lin1_kernel, cudaFuncAttributeMaxDynamicSharedMemorySize, LIN1_SMEM);
    cudaFuncSetAttribute(out_kernel,  cudaFuncAttributeMaxDynamicSharedMemorySize, OUT_SMEM);

    int ntile_n = (N + TN - 1) / TN;

    zero_agg_kernel<<<2048, 256>>>();
    lin1_kernel<<<ntile_n, 512, LIN1_SMEM>>>(x, lin1_w, N);
    edge_kernel<<<152, 512, EDGE_SMEM>>>(ea, eidx, ew,
                                         mlp_w1, mlp_b1, mlp_w2, mlp_b2, E);
    out_kernel<<<ntile_n, 512, OUT_SMEM>>>(lin2_w, lin2_b, lin_w, lin_b, out, N);
}